// round 2
// baseline (speedup 1.0000x reference)
#include <cuda_runtime.h>
#include <math.h>
#include <float.h>

#define Bz 2
#define Sz 2048
#define Dz 512
#define Hz 8
#define DPH 64
#define BH (Bz*Hz)
#define Mrows (Bz*Sz)

// scratch: projected q (as qm: time negated), k, v in (b,h,s,d) layout; softmax row stats
__device__ float g_q[(size_t)BH*Sz*DPH];
__device__ float g_k[(size_t)BH*Sz*DPH];
__device__ float g_v[(size_t)BH*Sz*DPH];
__device__ float g_m[BH*Sz];
__device__ float g_l[BH*Sz];

// ---------------------------------------------------------------------------
// Projection + Lorentz epilogue.  y = X @ W^T + b  (M=4096, N=512, K=512)
// BN=64 == one head chunk -> per-row space-norm reduction stays in-block.
// ---------------------------------------------------------------------------
__global__ __launch_bounds__(256) void proj_kernel(
    const float* __restrict__ X, const float* __restrict__ W,
    const float* __restrict__ bias, const float* __restrict__ lsc,
    int which, int negate)
{
    float* out = (which == 0) ? g_q : (which == 1) ? g_k : g_v;

    __shared__ float As[16][65];
    __shared__ float Bs[16][65];
    __shared__ float red[64][17];
    __shared__ float timeSh[64];

    const int tid = threadIdx.x;
    const int tx = tid & 15, ty = tid >> 4;
    const int n0 = blockIdx.x * 64;
    const int m0 = blockIdx.y * 64;

    const int lr = tid >> 2;        // 0..63 row within tile
    const int lk = (tid & 3) * 4;   // 0,4,8,12 k-offset

    float acc[4][4];
#pragma unroll
    for (int i = 0; i < 4; i++)
#pragma unroll
        for (int j = 0; j < 4; j++) acc[i][j] = 0.f;

    for (int k0 = 0; k0 < Dz; k0 += 16) {
        float4 av = *reinterpret_cast<const float4*>(X + (size_t)(m0 + lr) * Dz + k0 + lk);
        float4 bv = *reinterpret_cast<const float4*>(W + (size_t)(n0 + lr) * Dz + k0 + lk);
        As[lk + 0][lr] = av.x; As[lk + 1][lr] = av.y; As[lk + 2][lr] = av.z; As[lk + 3][lr] = av.w;
        Bs[lk + 0][lr] = bv.x; Bs[lk + 1][lr] = bv.y; Bs[lk + 2][lr] = bv.z; Bs[lk + 3][lr] = bv.w;
        __syncthreads();
#pragma unroll
        for (int kk = 0; kk < 16; kk++) {
            float a[4], b[4];
#pragma unroll
            for (int i = 0; i < 4; i++) a[i] = As[kk][ty * 4 + i];
#pragma unroll
            for (int j = 0; j < 4; j++) b[j] = Bs[kk][tx * 4 + j];
#pragma unroll
            for (int i = 0; i < 4; i++)
#pragma unroll
                for (int j = 0; j < 4; j++) acc[i][j] = fmaf(a[i], b[j], acc[i][j]);
        }
        __syncthreads();
    }

    const float es = expf(lsc[0]);

    float y[4][4];
#pragma unroll
    for (int i = 0; i < 4; i++) {
        float p = 0.f;
#pragma unroll
        for (int j = 0; j < 4; j++) {
            int c = tx * 4 + j;
            float yy = acc[i][j] + bias[n0 + c];
            y[i][j] = yy;
            if (c != 0) p = fmaf(yy, yy, p);
        }
        red[ty * 4 + i][tx] = p;
    }
    __syncthreads();
    if (tx == 0) {
#pragma unroll
        for (int i = 0; i < 4; i++) {
            float t = 1.f / (1.f + expf(-y[i][0])) * es + 1.1f;
            timeSh[ty * 4 + i] = t;
        }
    }
    __syncthreads();

    const int h = n0 / 64;
#pragma unroll
    for (int i = 0; i < 4; i++) {
        int r = ty * 4 + i;
        float sq = 0.f;
#pragma unroll
        for (int u = 0; u < 16; u++) sq += red[r][u];
        sq = fmaxf(sq, 1e-8f);
        float t = timeSh[r];
        float f = sqrtf((t * t - 1.f) / sq);
        int m = m0 + r;
        int b = m / Sz, s = m % Sz;
        float* orow = out + (size_t)((b * Hz + h) * Sz + s) * DPH;
#pragma unroll
        for (int j = 0; j < 4; j++) {
            int c = tx * 4 + j;
            float o = (c == 0) ? (negate ? -t : t) : y[i][j] * f;
            orow[c] = o;
        }
    }
}

// ---------------------------------------------------------------------------
// Scores: raw score write + online (max, sumexp) per row.  Causal tiles only.
// ---------------------------------------------------------------------------
__global__ __launch_bounds__(256) void scores_kernel(
    float* __restrict__ attn,
    const float* __restrict__ scale_ptr, const float* __restrict__ bias_ptr)
{
    const int bh = blockIdx.y, qt = blockIdx.x;
    const int tid = threadIdx.x, tx = tid & 15, ty = tid >> 4;

    __shared__ float Qs[64][65];
    __shared__ float Ks[64][65];
    __shared__ float red[64][17];

    const float* Qg = g_q + (size_t)bh * Sz * DPH + (size_t)qt * 64 * DPH;
#pragma unroll
    for (int it = 0; it < 4; ++it) {
        int idx = tid + it * 256;
        int q = idx >> 4;
        int d4 = (idx & 15) * 4;
        float4 v = *reinterpret_cast<const float4*>(Qg + q * DPH + d4);
        Qs[d4 + 0][q] = v.x; Qs[d4 + 1][q] = v.y; Qs[d4 + 2][q] = v.z; Qs[d4 + 3][q] = v.w;
    }

    const float inv_as = 1.f / scale_ptr[0];
    const float ab = bias_ptr[0];

    float m_run[4], l_run[4];
#pragma unroll
    for (int i = 0; i < 4; i++) { m_run[i] = -FLT_MAX; l_run[i] = 0.f; }

    const float* Kg = g_k + (size_t)bh * Sz * DPH;
    float* arow = attn + (size_t)bh * Sz * Sz;

    for (int kt = 0; kt <= qt; ++kt) {
        __syncthreads();
#pragma unroll
        for (int it = 0; it < 4; ++it) {
            int idx = tid + it * 256;
            int r = idx >> 4;
            int d4 = (idx & 15) * 4;
            float4 v = *reinterpret_cast<const float4*>(Kg + (size_t)(kt * 64 + r) * DPH + d4);
            Ks[d4 + 0][r] = v.x; Ks[d4 + 1][r] = v.y; Ks[d4 + 2][r] = v.z; Ks[d4 + 3][r] = v.w;
        }
        __syncthreads();

        float acc[4][4];
#pragma unroll
        for (int i = 0; i < 4; i++)
#pragma unroll
            for (int j = 0; j < 4; j++) acc[i][j] = 0.f;
#pragma unroll
        for (int kk = 0; kk < 64; kk++) {
            float a[4], b[4];
#pragma unroll
            for (int i = 0; i < 4; i++) a[i] = Qs[kk][ty * 4 + i];
#pragma unroll
            for (int j = 0; j < 4; j++) b[j] = Ks[kk][tx * 4 + j];
#pragma unroll
            for (int i = 0; i < 4; i++)
#pragma unroll
                for (int j = 0; j < 4; j++) acc[i][j] = fmaf(a[i], b[j], acc[i][j]);
        }

        float sreg[4][4];
#pragma unroll
        for (int i = 0; i < 4; i++) {
            int gq = qt * 64 + ty * 4 + i;
#pragma unroll
            for (int j = 0; j < 4; j++) {
                int gk = kt * 64 + tx * 4 + j;
                float s = (2.f + 2.f * acc[i][j]) * inv_as + ab;
                if (gk > gq) s = -FLT_MAX;   // masked; overwritten with 0 in pass B
                sreg[i][j] = s;
            }
            float4 sv = make_float4(sreg[i][0], sreg[i][1], sreg[i][2], sreg[i][3]);
            *reinterpret_cast<float4*>(arow + (size_t)gq * Sz + kt * 64 + tx * 4) = sv;
        }

        // online stats
#pragma unroll
        for (int i = 0; i < 4; i++) {
            float pm = fmaxf(fmaxf(sreg[i][0], sreg[i][1]), fmaxf(sreg[i][2], sreg[i][3]));
            red[ty * 4 + i][tx] = pm;
        }
        __syncthreads();
        float newm[4];
#pragma unroll
        for (int i = 0; i < 4; i++) {
            float tm = -FLT_MAX;
#pragma unroll
            for (int u = 0; u < 16; u++) tm = fmaxf(tm, red[ty * 4 + i][u]);
            newm[i] = fmaxf(m_run[i], tm);
        }
        __syncthreads();
#pragma unroll
        for (int i = 0; i < 4; i++) {
            float pl = 0.f;
#pragma unroll
            for (int j = 0; j < 4; j++) pl += expf(sreg[i][j] - newm[i]);
            red[ty * 4 + i][tx] = pl;
        }
        __syncthreads();
#pragma unroll
        for (int i = 0; i < 4; i++) {
            float tl = 0.f;
#pragma unroll
            for (int u = 0; u < 16; u++) tl += red[ty * 4 + i][u];
            l_run[i] = l_run[i] * expf(m_run[i] - newm[i]) + tl;
            m_run[i] = newm[i];
        }
    }

    if (tx == 0) {
#pragma unroll
        for (int i = 0; i < 4; i++) {
            int gq = qt * 64 + ty * 4 + i;
            g_m[bh * Sz + gq] = m_run[i];
            g_l[bh * Sz + gq] = l_run[i];
        }
    }
}

// ---------------------------------------------------------------------------
// Normalize attn (incl. zeroing upper triangle) + attn@V + Lorentz context.
// ---------------------------------------------------------------------------
__global__ __launch_bounds__(256) void av_kernel(
    float* __restrict__ attn, float* __restrict__ ctx)
{
    const int bh = blockIdx.y, qt = blockIdx.x;
    const int b = bh / Hz, h = bh % Hz;
    const int tid = threadIdx.x, tx = tid & 15, ty = tid >> 4;

    __shared__ float Ps[64][65];   // [k][q] normalized probabilities
    __shared__ float Vs[64][65];   // [k][d]
    __shared__ float red[64][17];
    __shared__ float msh[64], ilsh[64];

    if (tid < 64) {
        msh[tid] = g_m[bh * Sz + qt * 64 + tid];
        ilsh[tid] = 1.f / g_l[bh * Sz + qt * 64 + tid];
    }

    float acc[4][4];
#pragma unroll
    for (int i = 0; i < 4; i++)
#pragma unroll
        for (int j = 0; j < 4; j++) acc[i][j] = 0.f;

    float* arow = attn + (size_t)bh * Sz * Sz;
    const float* Vg = g_v + (size_t)bh * Sz * DPH;

    const int NKT = Sz / 64;
    for (int kt = 0; kt < NKT; ++kt) {
        const bool live = (kt <= qt);
        __syncthreads();
#pragma unroll
        for (int it = 0; it < 4; ++it) {
            int idx = tid + it * 256;
            int q = idx >> 4;
            int c4 = (idx & 15) * 4;
            int gq = qt * 64 + q;
            size_t off = (size_t)gq * Sz + kt * 64 + c4;
            float4 p = make_float4(0.f, 0.f, 0.f, 0.f);
            if (live) {
                float4 s = *reinterpret_cast<const float4*>(arow + off);
                float mm = msh[q], il = ilsh[q];
                int gk = kt * 64 + c4;
                p.x = (gk + 0 <= gq) ? expf(s.x - mm) * il : 0.f;
                p.y = (gk + 1 <= gq) ? expf(s.y - mm) * il : 0.f;
                p.z = (gk + 2 <= gq) ? expf(s.z - mm) * il : 0.f;
                p.w = (gk + 3 <= gq) ? expf(s.w - mm) * il : 0.f;
                Ps[c4 + 0][q] = p.x; Ps[c4 + 1][q] = p.y;
                Ps[c4 + 2][q] = p.z; Ps[c4 + 3][q] = p.w;
            }
            *reinterpret_cast<float4*>(arow + off) = p;   // final attn (0 above diag)
        }
        if (live) {
#pragma unroll
            for (int it = 0; it < 4; ++it) {
                int idx = tid + it * 256;
                int r = idx >> 4;
                int d4 = (idx & 15) * 4;
                float4 v = *reinterpret_cast<const float4*>(Vg + (size_t)(kt * 64 + r) * DPH + d4);
                Vs[r][d4 + 0] = v.x; Vs[r][d4 + 1] = v.y; Vs[r][d4 + 2] = v.z; Vs[r][d4 + 3] = v.w;
            }
        }
        __syncthreads();
        if (live) {
#pragma unroll
            for (int kk = 0; kk < 64; kk++) {
                float p[4], v[4];
#pragma unroll
                for (int i = 0; i < 4; i++) p[i] = Ps[kk][ty * 4 + i];
#pragma unroll
                for (int j = 0; j < 4; j++) v[j] = Vs[kk][tx * 4 + j];
#pragma unroll
                for (int i = 0; i < 4; i++)
#pragma unroll
                    for (int j = 0; j < 4; j++) acc[i][j] = fmaf(p[i], v[j], acc[i][j]);
            }
        }
    }

    // Lorentz context normalization: inner = -ave0^2 + sum(ave_rest^2)
#pragma unroll
    for (int i = 0; i < 4; i++) {
        float pp = 0.f;
#pragma unroll
        for (int j = 0; j < 4; j++) {
            int d = tx * 4 + j;
            float a = acc[i][j];
            pp += (d == 0) ? -a * a : a * a;
        }
        red[ty * 4 + i][tx] = pp;
    }
    __syncthreads();
#pragma unroll
    for (int i = 0; i < 4; i++) {
        int r = ty * 4 + i;
        float inner = 0.f;
#pragma unroll
        for (int u = 0; u < 16; u++) inner += red[r][u];
        float denom = sqrtf(fmaxf(fabsf(inner), 1e-8f));
        float inv = 1.f / denom;
        int gq = qt * 64 + r;
        float* crow = ctx + (size_t)((b * Sz + gq) * Hz + h) * DPH + tx * 4;
#pragma unroll
        for (int j = 0; j < 4; j++) crow[j] = acc[i][j] * inv;
    }
}

extern "C" void kernel_launch(void* const* d_in, const int* in_sizes, int n_in,
                              void* d_out, int out_size)
{
    const float* key   = (const float*)d_in[0];
    const float* value = (const float*)d_in[1];
    const float* query = (const float*)d_in[2];
    // d_in[3] = mask (strict upper triangle); applied analytically by index.
    const float* Wq = (const float*)d_in[4];
    const float* bq = (const float*)d_in[5];
    const float* sq = (const float*)d_in[6];
    const float* Wk = (const float*)d_in[7];
    const float* bk = (const float*)d_in[8];
    const float* sk = (const float*)d_in[9];
    const float* Wv = (const float*)d_in[10];
    const float* bv = (const float*)d_in[11];
    const float* sv = (const float*)d_in[12];
    const float* att_scale = (const float*)d_in[13];
    const float* att_bias  = (const float*)d_in[14];

    float* ctx  = (float*)d_out;
    float* attn = ctx + (size_t)Bz * Sz * Dz;   // output tuple: (context, attn)

    dim3 gp(Dz / 64, Mrows / 64);
    proj_kernel<<<gp, 256>>>(query, Wq, bq, sq, 0, 1);  // store qm (time negated)
    proj_kernel<<<gp, 256>>>(key,   Wk, bk, sk, 1, 0);
    proj_kernel<<<gp, 256>>>(value, Wv, bv, sv, 2, 0);

    dim3 ga(Sz / 64, BH);
    scores_kernel<<<ga, 256>>>(attn, att_scale, att_bias);
    av_kernel<<<ga, 256>>>(attn, ctx);
}

// round 3
// speedup vs baseline: 1.5238x; 1.5238x over previous
#include <cuda_runtime.h>
#include <math.h>

#define Bz 2
#define Sz 2048
#define Dz 512
#define Hz 8
#define DPH 64
#define BHn (Bz*Hz)
#define Mrows (Bz*Sz)
#define QT 128
#define NQT (Sz/QT)

__device__ float g_q[(size_t)BHn*Sz*DPH];
__device__ float g_k[(size_t)BHn*Sz*DPH];
__device__ float g_v[(size_t)BHn*Sz*DPH];
__device__ float g_l[BHn*Sz];

// ---------------------------------------------------------------------------
// Fused projections: y = X @ W^T + b, Lorentz hyperboloid epilogue.
// 128x128 tile, 256 threads, 8x8 per thread. z: 0=q(qm) 1=k 2=v
// ---------------------------------------------------------------------------
__global__ __launch_bounds__(256) void proj_kernel(
    const float* __restrict__ Xq, const float* __restrict__ Wq, const float* __restrict__ bq, const float* __restrict__ sq,
    const float* __restrict__ Xk, const float* __restrict__ Wk, const float* __restrict__ bk, const float* __restrict__ sk,
    const float* __restrict__ Xv, const float* __restrict__ Wv, const float* __restrict__ bv, const float* __restrict__ sv)
{
    const int z = blockIdx.z;
    const float* X    = (z==0)?Xq:(z==1)?Xk:Xv;
    const float* W    = (z==0)?Wq:(z==1)?Wk:Wv;
    const float* bias = (z==0)?bq:(z==1)?bk:bv;
    const float* lsc  = (z==0)?sq:(z==1)?sk:sv;
    float* out = (z==0)?g_q:(z==1)?g_k:g_v;

    __shared__ float As[16*132];
    __shared__ float Bs[16*132];
    __shared__ float red[128*17];
    __shared__ float tsh[256];
    __shared__ float fsh[256];

    const int tid = threadIdx.x;
    const int tx = tid & 15, ty = tid >> 4;
    const int n0 = blockIdx.x * 128;
    const int m0 = blockIdx.y * 128;
    const int lr = tid >> 1;   // 0..127
    const int lh = tid & 1;

    float acc[8][8];
#pragma unroll
    for (int i = 0; i < 8; i++)
#pragma unroll
        for (int j = 0; j < 8; j++) acc[i][j] = 0.f;

    const float* Xp = X + (size_t)(m0 + lr) * Dz + lh * 8;
    const float* Wp = W + (size_t)(n0 + lr) * Dz + lh * 8;
    const int cb = lr & 7;
    const int mg = lr >> 3;
    const int kb = lh * 8;
    const int c0 = ((mg ^ (lh * 2)) << 3) + cb;
    const int c1 = ((mg ^ (lh * 2 + 1)) << 3) + cb;

    for (int k0 = 0; k0 < Dz; k0 += 16) {
        float4 a0 = *(const float4*)(Xp + k0);
        float4 a1 = *(const float4*)(Xp + k0 + 4);
        float4 b0 = *(const float4*)(Wp + k0);
        float4 b1 = *(const float4*)(Wp + k0 + 4);
        __syncthreads();
        As[(kb+0)*132+c0]=a0.x; As[(kb+1)*132+c0]=a0.y; As[(kb+2)*132+c0]=a0.z; As[(kb+3)*132+c0]=a0.w;
        As[(kb+4)*132+c1]=a1.x; As[(kb+5)*132+c1]=a1.y; As[(kb+6)*132+c1]=a1.z; As[(kb+7)*132+c1]=a1.w;
        Bs[(kb+0)*132+c0]=b0.x; Bs[(kb+1)*132+c0]=b0.y; Bs[(kb+2)*132+c0]=b0.z; Bs[(kb+3)*132+c0]=b0.w;
        Bs[(kb+4)*132+c1]=b1.x; Bs[(kb+5)*132+c1]=b1.y; Bs[(kb+6)*132+c1]=b1.z; Bs[(kb+7)*132+c1]=b1.w;
        __syncthreads();
#pragma unroll
        for (int kk = 0; kk < 16; kk++) {
            int sw = (kk >> 2) & 3;
            const float* ap = &As[kk*132 + ((ty ^ sw) << 3)];
            const float* bp = &Bs[kk*132 + ((tx ^ sw) << 3)];
            float a[8], b[8];
            *(float4*)(a)   = *(const float4*)(ap);
            *(float4*)(a+4) = *(const float4*)(ap+4);
            *(float4*)(b)   = *(const float4*)(bp);
            *(float4*)(b+4) = *(const float4*)(bp+4);
#pragma unroll
            for (int i = 0; i < 8; i++)
#pragma unroll
                for (int j = 0; j < 8; j++) acc[i][j] = fmaf(a[i], b[j], acc[i][j]);
        }
    }

    const float es = expf(lsc[0]);
    float b8[8];
#pragma unroll
    for (int j = 0; j < 8; j++) b8[j] = bias[n0 + tx*8 + j];

#pragma unroll
    for (int i = 0; i < 8; i++) {
        float ps = 0.f;
#pragma unroll
        for (int j = 0; j < 8; j++) {
            float y = acc[i][j] + b8[j];
            acc[i][j] = y;
            if ((((tx & 7) << 3) | j) != 0) ps = fmaf(y, y, ps);  // exclude lc==0 (time)
        }
        red[(ty*8+i)*17 + tx] = ps;
    }
    __syncthreads();
    if ((tx & 7) == 0) {
#pragma unroll
        for (int i = 0; i < 8; i++) {
            int r = ty*8 + i;
            float sqs = 0.f;
#pragma unroll
            for (int u = 0; u < 8; u++) sqs += red[r*17 + tx + u];
            sqs = fmaxf(sqs, 1e-8f);
            float t = es / (1.f + expf(-acc[i][0])) + 1.1f;
            float f = sqrtf((t*t - 1.f) / sqs);
            int ch = tx >> 3;
            tsh[r*2 + ch] = t;
            fsh[r*2 + ch] = f;
        }
    }
    __syncthreads();
    const int hbase = n0 >> 6;
#pragma unroll
    for (int i = 0; i < 8; i++) {
        int m = m0 + ty*8 + i;
        int bb = m >> 11, s = m & (Sz - 1);
        int ch = tx >> 3;
        int h = hbase + ch;
        float t = tsh[(ty*8+i)*2 + ch];
        float f = fsh[(ty*8+i)*2 + ch];
        float o[8];
#pragma unroll
        for (int j = 0; j < 8; j++) {
            int lc = ((tx & 7) << 3) + j;
            o[j] = (lc == 0) ? ((z == 0) ? -t : t) : acc[i][j] * f;
        }
        float* orow = out + ((size_t)((bb*Hz + h)*Sz + s)) * DPH + (tx & 7) * 8;
        *(float4*)(orow)     = *(float4*)(o);
        *(float4*)(orow + 4) = *(float4*)(o + 4);
    }
}

// ---------------------------------------------------------------------------
// Fused causal attention: S^T (128k x 128q), P = exp(score) (bounded <= 0,
// no max needed; att_bias dropped via shift-invariance), raw P -> gmem,
// ctx += P^T V in regs, Lorentz ctx epilogue (1/l cancels). Row sums -> g_l.
// ---------------------------------------------------------------------------
__global__ __launch_bounds__(256) void attn_kernel(
    float* __restrict__ attn, float* __restrict__ ctx,
    const float* __restrict__ scale_ptr)
{
    extern __shared__ float sm[];
    float* Qs  = sm;            // [64][132]  d-major, swizzled
    float* KV  = sm + 8448;     // union: K [64][132] / V [128][68]
    float* Ps  = KV + 8704;     // [128][132] k-major, swizzled
    float* RED = Ps + 16896;    // [128][17]

    const int blk = blockIdx.x;
    const int bh = blk & 15;
    const int qt = (NQT - 1) - (blk >> 4);   // heavy tiles first
    const int q0 = qt * QT;
    const int b = bh >> 3, h = bh & 7;

    const int tid = threadIdx.x;
    const int tx = tid & 15, ty = tid >> 4;
    const int dx = tid & 7,  qy = tid >> 3;

    const float inv_as = 1.f / scale_ptr[0];

    const float* Qg = g_q + (size_t)bh * Sz * DPH;
    const float* Kg = g_k + (size_t)bh * Sz * DPH;
    const float* Vg = g_v + (size_t)bh * Sz * DPH;
    float* arow = attn + (size_t)bh * Sz * Sz;

    // Q tile -> smem [d][q], swizzled
#pragma unroll
    for (int it = 0; it < 8; it++) {
        int idx = tid + it * 256;
        int q = idx >> 4, d4 = (idx & 15) * 4;
        float4 v = *(const float4*)(Qg + (size_t)(q0 + q) * DPH + d4);
        int col = (((q >> 3) ^ ((d4 >> 2) & 3)) << 3) + (q & 7);
        Qs[(d4+0)*132+col]=v.x; Qs[(d4+1)*132+col]=v.y; Qs[(d4+2)*132+col]=v.z; Qs[(d4+3)*132+col]=v.w;
    }

    float acc2[4][8];
#pragma unroll
    for (int qi = 0; qi < 4; qi++)
#pragma unroll
        for (int dj = 0; dj < 8; dj++) acc2[qi][dj] = 0.f;
    float lpart[8];
#pragma unroll
    for (int j = 0; j < 8; j++) lpart[j] = 0.f;

    for (int kt = 0; kt <= qt; ++kt) {
        const int k0 = kt * QT;
        __syncthreads();   // previous PV done with KV/Ps
        // K tile -> smem [d][k], swizzled
#pragma unroll
        for (int it = 0; it < 8; it++) {
            int idx = tid + it * 256;
            int k = idx >> 4, d4 = (idx & 15) * 4;
            float4 v = *(const float4*)(Kg + (size_t)(k0 + k) * DPH + d4);
            int col = (((k >> 3) ^ ((d4 >> 2) & 3)) << 3) + (k & 7);
            KV[(d4+0)*132+col]=v.x; KV[(d4+1)*132+col]=v.y; KV[(d4+2)*132+col]=v.z; KV[(d4+3)*132+col]=v.w;
        }
        __syncthreads();

        // S^T[k][q]: rows k = ty*8+i, cols q = tx*8+j
        float accS[8][8];
#pragma unroll
        for (int i = 0; i < 8; i++)
#pragma unroll
            for (int j = 0; j < 8; j++) accS[i][j] = 0.f;
#pragma unroll 4
        for (int kk = 0; kk < 64; kk++) {
            int sw = (kk >> 2) & 3;
            const float* ap = &KV[kk*132 + ((ty ^ sw) << 3)];
            const float* bp = &Qs[kk*132 + ((tx ^ sw) << 3)];
            float a[8], bb[8];
            *(float4*)(a)    = *(const float4*)(ap);
            *(float4*)(a+4)  = *(const float4*)(ap+4);
            *(float4*)(bb)   = *(const float4*)(bp);
            *(float4*)(bb+4) = *(const float4*)(bp+4);
#pragma unroll
            for (int i = 0; i < 8; i++)
#pragma unroll
                for (int j = 0; j < 8; j++) accS[i][j] = fmaf(a[i], bb[j], accS[i][j]);
        }

        // exp + causal mask + row-sum partials + gmem store (unnormalized P)
#pragma unroll
        for (int j = 0; j < 8; j++) {
            int gq = q0 + tx*8 + j;
#pragma unroll
            for (int i = 0; i < 8; i++) {
                int gk = k0 + ty*8 + i;
                float p = 0.f;
                if (gk <= gq) p = expf((2.f*accS[i][j] + 2.f) * inv_as);
                accS[i][j] = p;
                lpart[j] += p;
            }
            float4 w0 = make_float4(accS[0][j], accS[1][j], accS[2][j], accS[3][j]);
            float4 w1 = make_float4(accS[4][j], accS[5][j], accS[6][j], accS[7][j]);
            float* dst = arow + (size_t)gq * Sz + k0 + ty*8;
            *(float4*)(dst)     = w0;
            *(float4*)(dst + 4) = w1;
        }
        // P -> smem [k][q], swizzled
#pragma unroll
        for (int i = 0; i < 8; i++) {
            int row = ty*8 + i;
            int cg = (tx ^ ((row >> 2) & 3)) << 3;
            float4 w0 = make_float4(accS[i][0], accS[i][1], accS[i][2], accS[i][3]);
            float4 w1 = make_float4(accS[i][4], accS[i][5], accS[i][6], accS[i][7]);
            *(float4*)(&Ps[row*132 + cg])     = w0;
            *(float4*)(&Ps[row*132 + cg + 4]) = w1;
        }
        __syncthreads();   // done reading K, done writing Ps
        // V tile -> smem [k][d]
#pragma unroll
        for (int it = 0; it < 8; it++) {
            int idx = tid + it * 256;
            int k = idx >> 4, d4 = (idx & 15) * 4;
            float4 v = *(const float4*)(Vg + (size_t)(k0 + k) * DPH + d4);
            *(float4*)(&KV[k*68 + d4]) = v;
        }
        __syncthreads();
        // ctx[q][d] += P[k][q] * V[k][d];  q = 4*qy+qi, d = dx*8+dj
#pragma unroll 4
        for (int kk = 0; kk < 128; kk++) {
            int sw = (kk >> 2) & 3;
            const float* pp = &Ps[kk*132 + (((qy >> 1) ^ sw) << 3) + ((qy & 1) << 2)];
            float4 pa = *(const float4*)pp;
            const float* vp = &KV[kk*68 + dx*8];
            float4 v0 = *(const float4*)vp;
            float4 v1 = *(const float4*)(vp + 4);
            float aa[4] = {pa.x, pa.y, pa.z, pa.w};
            float vv[8] = {v0.x, v0.y, v0.z, v0.w, v1.x, v1.y, v1.z, v1.w};
#pragma unroll
            for (int qi = 0; qi < 4; qi++)
#pragma unroll
                for (int dj = 0; dj < 8; dj++)
                    acc2[qi][dj] = fmaf(aa[qi], vv[dj], acc2[qi][dj]);
        }
    }

    // row sums l -> g_l (for the normalize pass)
    __syncthreads();
#pragma unroll
    for (int j = 0; j < 8; j++) RED[(tx*8 + j)*17 + ty] = lpart[j];
    __syncthreads();
    if (tid < 128) {
        float l = 0.f;
#pragma unroll
        for (int u = 0; u < 16; u++) l += RED[tid*17 + u];
        g_l[bh*Sz + q0 + tid] = l;
    }

    // Lorentz context epilogue (1/l cancels): 8-lane shuffle reduce over d
#pragma unroll
    for (int qi = 0; qi < 4; qi++) {
        float pp = 0.f;
#pragma unroll
        for (int dj = 0; dj < 8; dj++) {
            float a = acc2[qi][dj];
            pp += ((dx == 0) && (dj == 0)) ? -a*a : a*a;
        }
#pragma unroll
        for (int off = 4; off >= 1; off >>= 1)
            pp += __shfl_xor_sync(0xffffffffu, pp, off, 8);
        float inv = rsqrtf(fmaxf(fabsf(pp), 1e-8f));
        int gq = q0 + qy*4 + qi;
        float* crow = ctx + ((size_t)((b*Sz + gq)*Hz + h)) * DPH + dx*8;
        float o[8];
#pragma unroll
        for (int dj = 0; dj < 8; dj++) o[dj] = acc2[qi][dj] * inv;
        *(float4*)(crow)     = *(float4*)(o);
        *(float4*)(crow + 4) = *(float4*)(o + 4);
    }
}

// ---------------------------------------------------------------------------
// attn normalize: lower triangle *= 1/l, upper triangle = 0.
// ---------------------------------------------------------------------------
__global__ __launch_bounds__(256) void norm_kernel(float* __restrict__ attn)
{
    const int q = blockIdx.x;
    const int bh = blockIdx.y;
    const float inv = 1.f / g_l[bh*Sz + q];
    float4* row = (float4*)(attn + (size_t)bh * Sz * Sz + (size_t)q * Sz);
    const float4 zero = make_float4(0.f, 0.f, 0.f, 0.f);
#pragma unroll
    for (int it = 0; it < 2; it++) {
        int p = threadIdx.x + it * 256;     // float4 index, 512 per row
        if (p * 4 > q) {
            row[p] = zero;
        } else {
            float4 v = row[p];               // entries past diag already 0
            v.x *= inv; v.y *= inv; v.z *= inv; v.w *= inv;
            row[p] = v;
        }
    }
}

extern "C" void kernel_launch(void* const* d_in, const int* in_sizes, int n_in,
                              void* d_out, int out_size)
{
    const float* key   = (const float*)d_in[0];
    const float* value = (const float*)d_in[1];
    const float* query = (const float*)d_in[2];
    // d_in[3] = mask (strict upper triangle), applied analytically
    const float* Wq = (const float*)d_in[4];
    const float* bq = (const float*)d_in[5];
    const float* sq = (const float*)d_in[6];
    const float* Wk = (const float*)d_in[7];
    const float* bk = (const float*)d_in[8];
    const float* sk = (const float*)d_in[9];
    const float* Wv = (const float*)d_in[10];
    const float* bv = (const float*)d_in[11];
    const float* sv = (const float*)d_in[12];
    const float* att_scale = (const float*)d_in[13];

    float* ctx  = (float*)d_out;
    float* attn = ctx + (size_t)Bz * Sz * Dz;

    dim3 gp(Dz / 128, Mrows / 128, 3);
    proj_kernel<<<gp, 256>>>(query, Wq, bq, sq, key, Wk, bk, sk, value, Wv, bv, sv);

    static const int smem_bytes = (8448 + 8704 + 16896 + 128*17) * 4;
    cudaFuncSetAttribute(attn_kernel, cudaFuncAttributeMaxDynamicSharedMemorySize, smem_bytes);
    attn_kernel<<<BHn * NQT, 256, smem_bytes>>>(attn, ctx, att_scale);

    dim3 gn(Sz, BHn);
    norm_kernel<<<gn, 256>>>(attn);
}

// round 4
// speedup vs baseline: 1.5280x; 1.0028x over previous
#include <cuda_runtime.h>
#include <math.h>

#define Bz 2
#define Sz 2048
#define Dz 512
#define Hz 8
#define DPH 64
#define BHn (Bz*Hz)
#define Mrows (Bz*Sz)
#define QT 128
#define NQT (Sz/QT)

__device__ float g_q[(size_t)BHn*Sz*DPH];
__device__ float g_k[(size_t)BHn*Sz*DPH];
__device__ float g_v[(size_t)BHn*Sz*DPH];
__device__ float g_l[BHn*Sz];

// ---------------------------------------------------------------------------
// Fused projections: y = X @ W^T + b, Lorentz hyperboloid epilogue.
// 128x128 tile, 256 threads, 8x8 per thread. z: 0=q(qm) 1=k 2=v
// ---------------------------------------------------------------------------
__global__ __launch_bounds__(256) void proj_kernel(
    const float* __restrict__ Xq, const float* __restrict__ Wq, const float* __restrict__ bq, const float* __restrict__ sq,
    const float* __restrict__ Xk, const float* __restrict__ Wk, const float* __restrict__ bk, const float* __restrict__ sk,
    const float* __restrict__ Xv, const float* __restrict__ Wv, const float* __restrict__ bv, const float* __restrict__ sv)
{
    const int z = blockIdx.z;
    const float* X    = (z==0)?Xq:(z==1)?Xk:Xv;
    const float* W    = (z==0)?Wq:(z==1)?Wk:Wv;
    const float* bias = (z==0)?bq:(z==1)?bk:bv;
    const float* lsc  = (z==0)?sq:(z==1)?sk:sv;
    float* out = (z==0)?g_q:(z==1)?g_k:g_v;

    __shared__ float As[16*132];
    __shared__ float Bs[16*132];
    __shared__ float red[128*17];
    __shared__ float tsh[256];
    __shared__ float fsh[256];

    const int tid = threadIdx.x;
    const int tx = tid & 15, ty = tid >> 4;
    const int n0 = blockIdx.x * 128;
    const int m0 = blockIdx.y * 128;
    const int lr = tid >> 1;   // 0..127
    const int lh = tid & 1;

    float acc[8][8];
#pragma unroll
    for (int i = 0; i < 8; i++)
#pragma unroll
        for (int j = 0; j < 8; j++) acc[i][j] = 0.f;

    const float* Xp = X + (size_t)(m0 + lr) * Dz + lh * 8;
    const float* Wp = W + (size_t)(n0 + lr) * Dz + lh * 8;
    const int cb = lr & 7;
    const int mg = lr >> 3;
    const int kb = lh * 8;
    const int c0 = ((mg ^ (lh * 2)) << 3) + cb;
    const int c1 = ((mg ^ (lh * 2 + 1)) << 3) + cb;

    for (int k0 = 0; k0 < Dz; k0 += 16) {
        float4 a0 = *(const float4*)(Xp + k0);
        float4 a1 = *(const float4*)(Xp + k0 + 4);
        float4 b0 = *(const float4*)(Wp + k0);
        float4 b1 = *(const float4*)(Wp + k0 + 4);
        __syncthreads();
        As[(kb+0)*132+c0]=a0.x; As[(kb+1)*132+c0]=a0.y; As[(kb+2)*132+c0]=a0.z; As[(kb+3)*132+c0]=a0.w;
        As[(kb+4)*132+c1]=a1.x; As[(kb+5)*132+c1]=a1.y; As[(kb+6)*132+c1]=a1.z; As[(kb+7)*132+c1]=a1.w;
        Bs[(kb+0)*132+c0]=b0.x; Bs[(kb+1)*132+c0]=b0.y; Bs[(kb+2)*132+c0]=b0.z; Bs[(kb+3)*132+c0]=b0.w;
        Bs[(kb+4)*132+c1]=b1.x; Bs[(kb+5)*132+c1]=b1.y; Bs[(kb+6)*132+c1]=b1.z; Bs[(kb+7)*132+c1]=b1.w;
        __syncthreads();
#pragma unroll
        for (int kk = 0; kk < 16; kk++) {
            int sw = (kk >> 2) & 3;
            const float* ap = &As[kk*132 + ((ty ^ sw) << 3)];
            const float* bp = &Bs[kk*132 + ((tx ^ sw) << 3)];
            float a[8], b[8];
            *(float4*)(a)   = *(const float4*)(ap);
            *(float4*)(a+4) = *(const float4*)(ap+4);
            *(float4*)(b)   = *(const float4*)(bp);
            *(float4*)(b+4) = *(const float4*)(bp+4);
#pragma unroll
            for (int i = 0; i < 8; i++)
#pragma unroll
                for (int j = 0; j < 8; j++) acc[i][j] = fmaf(a[i], b[j], acc[i][j]);
        }
    }

    const float es = expf(lsc[0]);
    float b8[8];
#pragma unroll
    for (int j = 0; j < 8; j++) b8[j] = bias[n0 + tx*8 + j];

#pragma unroll
    for (int i = 0; i < 8; i++) {
        float ps = 0.f;
#pragma unroll
        for (int j = 0; j < 8; j++) {
            float y = acc[i][j] + b8[j];
            acc[i][j] = y;
            if ((((tx & 7) << 3) | j) != 0) ps = fmaf(y, y, ps);  // exclude lc==0 (time)
        }
        red[(ty*8+i)*17 + tx] = ps;
    }
    __syncthreads();
    if ((tx & 7) == 0) {
#pragma unroll
        for (int i = 0; i < 8; i++) {
            int r = ty*8 + i;
            float sqs = 0.f;
#pragma unroll
            for (int u = 0; u < 8; u++) sqs += red[r*17 + tx + u];
            sqs = fmaxf(sqs, 1e-8f);
            float t = es / (1.f + expf(-acc[i][0])) + 1.1f;
            float f = sqrtf((t*t - 1.f) / sqs);
            int ch = tx >> 3;
            tsh[r*2 + ch] = t;
            fsh[r*2 + ch] = f;
        }
    }
    __syncthreads();
    const int hbase = n0 >> 6;
#pragma unroll
    for (int i = 0; i < 8; i++) {
        int m = m0 + ty*8 + i;
        int bb = m >> 11, s = m & (Sz - 1);
        int ch = tx >> 3;
        int h = hbase + ch;
        float t = tsh[(ty*8+i)*2 + ch];
        float f = fsh[(ty*8+i)*2 + ch];
        float o[8];
#pragma unroll
        for (int j = 0; j < 8; j++) {
            int lc = ((tx & 7) << 3) + j;
            o[j] = (lc == 0) ? ((z == 0) ? -t : t) : acc[i][j] * f;
        }
        float* orow = out + ((size_t)((bb*Hz + h)*Sz + s)) * DPH + (tx & 7) * 8;
        *(float4*)(orow)     = *(float4*)(o);
        *(float4*)(orow + 4) = *(float4*)(o + 4);
    }
}

// ---------------------------------------------------------------------------
// Fused causal attention: S^T (128k x 128q), P = exp(score) (bounded <= 0,
// no max needed; att_bias dropped via shift-invariance), raw P -> gmem,
// ctx += P^T V in regs, Lorentz ctx epilogue (1/l cancels). Row sums -> g_l.
// ---------------------------------------------------------------------------
__global__ __launch_bounds__(256) void attn_kernel(
    float* __restrict__ attn, float* __restrict__ ctx,
    const float* __restrict__ scale_ptr)
{
    extern __shared__ float sm[];
    float* Qs  = sm;            // [64][132]  d-major, swizzled
    float* KV  = sm + 8448;     // union: K [64][132] / V [128][68]
    float* Ps  = KV + 8704;     // [128][132] k-major, swizzled
    float* RED = Ps + 16896;    // [128][17]

    const int blk = blockIdx.x;
    const int bh = blk & 15;
    const int qt = (NQT - 1) - (blk >> 4);   // heavy tiles first
    const int q0 = qt * QT;
    const int b = bh >> 3, h = bh & 7;

    const int tid = threadIdx.x;
    const int tx = tid & 15, ty = tid >> 4;
    const int dx = tid & 7,  qy = tid >> 3;

    const float inv_as = 1.f / scale_ptr[0];

    const float* Qg = g_q + (size_t)bh * Sz * DPH;
    const float* Kg = g_k + (size_t)bh * Sz * DPH;
    const float* Vg = g_v + (size_t)bh * Sz * DPH;
    float* arow = attn + (size_t)bh * Sz * Sz;

    // Q tile -> smem [d][q], swizzled
#pragma unroll
    for (int it = 0; it < 8; it++) {
        int idx = tid + it * 256;
        int q = idx >> 4, d4 = (idx & 15) * 4;
        float4 v = *(const float4*)(Qg + (size_t)(q0 + q) * DPH + d4);
        int col = (((q >> 3) ^ ((d4 >> 2) & 3)) << 3) + (q & 7);
        Qs[(d4+0)*132+col]=v.x; Qs[(d4+1)*132+col]=v.y; Qs[(d4+2)*132+col]=v.z; Qs[(d4+3)*132+col]=v.w;
    }

    float acc2[4][8];
#pragma unroll
    for (int qi = 0; qi < 4; qi++)
#pragma unroll
        for (int dj = 0; dj < 8; dj++) acc2[qi][dj] = 0.f;
    float lpart[8];
#pragma unroll
    for (int j = 0; j < 8; j++) lpart[j] = 0.f;

    for (int kt = 0; kt <= qt; ++kt) {
        const int k0 = kt * QT;
        __syncthreads();   // previous PV done with KV/Ps
        // K tile -> smem [d][k], swizzled
#pragma unroll
        for (int it = 0; it < 8; it++) {
            int idx = tid + it * 256;
            int k = idx >> 4, d4 = (idx & 15) * 4;
            float4 v = *(const float4*)(Kg + (size_t)(k0 + k) * DPH + d4);
            int col = (((k >> 3) ^ ((d4 >> 2) & 3)) << 3) + (k & 7);
            KV[(d4+0)*132+col]=v.x; KV[(d4+1)*132+col]=v.y; KV[(d4+2)*132+col]=v.z; KV[(d4+3)*132+col]=v.w;
        }
        __syncthreads();

        // S^T[k][q]: rows k = ty*8+i, cols q = tx*8+j
        float accS[8][8];
#pragma unroll
        for (int i = 0; i < 8; i++)
#pragma unroll
            for (int j = 0; j < 8; j++) accS[i][j] = 0.f;
#pragma unroll 4
        for (int kk = 0; kk < 64; kk++) {
            int sw = (kk >> 2) & 3;
            const float* ap = &KV[kk*132 + ((ty ^ sw) << 3)];
            const float* bp = &Qs[kk*132 + ((tx ^ sw) << 3)];
            float a[8], bb[8];
            *(float4*)(a)    = *(const float4*)(ap);
            *(float4*)(a+4)  = *(const float4*)(ap+4);
            *(float4*)(bb)   = *(const float4*)(bp);
            *(float4*)(bb+4) = *(const float4*)(bp+4);
#pragma unroll
            for (int i = 0; i < 8; i++)
#pragma unroll
                for (int j = 0; j < 8; j++) accS[i][j] = fmaf(a[i], bb[j], accS[i][j]);
        }

        // exp + causal mask + row-sum partials + gmem store (unnormalized P)
#pragma unroll
        for (int j = 0; j < 8; j++) {
            int gq = q0 + tx*8 + j;
#pragma unroll
            for (int i = 0; i < 8; i++) {
                int gk = k0 + ty*8 + i;
                float p = 0.f;
                if (gk <= gq) p = expf((2.f*accS[i][j] + 2.f) * inv_as);
                accS[i][j] = p;
                lpart[j] += p;
            }
            float4 w0 = make_float4(accS[0][j], accS[1][j], accS[2][j], accS[3][j]);
            float4 w1 = make_float4(accS[4][j], accS[5][j], accS[6][j], accS[7][j]);
            float* dst = arow + (size_t)gq * Sz + k0 + ty*8;
            *(float4*)(dst)     = w0;
            *(float4*)(dst + 4) = w1;
        }
        // P -> smem [k][q], swizzled
#pragma unroll
        for (int i = 0; i < 8; i++) {
            int row = ty*8 + i;
            int cg = (tx ^ ((row >> 2) & 3)) << 3;
            float4 w0 = make_float4(accS[i][0], accS[i][1], accS[i][2], accS[i][3]);
            float4 w1 = make_float4(accS[i][4], accS[i][5], accS[i][6], accS[i][7]);
            *(float4*)(&Ps[row*132 + cg])     = w0;
            *(float4*)(&Ps[row*132 + cg + 4]) = w1;
        }
        __syncthreads();   // done reading K, done writing Ps
        // V tile -> smem [k][d]
#pragma unroll
        for (int it = 0; it < 8; it++) {
            int idx = tid + it * 256;
            int k = idx >> 4, d4 = (idx & 15) * 4;
            float4 v = *(const float4*)(Vg + (size_t)(k0 + k) * DPH + d4);
            *(float4*)(&KV[k*68 + d4]) = v;
        }
        __syncthreads();
        // ctx[q][d] += P[k][q] * V[k][d];  q = 4*qy+qi, d = dx*8+dj
#pragma unroll 4
        for (int kk = 0; kk < 128; kk++) {
            int sw = (kk >> 2) & 3;
            const float* pp = &Ps[kk*132 + (((qy >> 1) ^ sw) << 3) + ((qy & 1) << 2)];
            float4 pa = *(const float4*)pp;
            const float* vp = &KV[kk*68 + dx*8];
            float4 v0 = *(const float4*)vp;
            float4 v1 = *(const float4*)(vp + 4);
            float aa[4] = {pa.x, pa.y, pa.z, pa.w};
            float vv[8] = {v0.x, v0.y, v0.z, v0.w, v1.x, v1.y, v1.z, v1.w};
#pragma unroll
            for (int qi = 0; qi < 4; qi++)
#pragma unroll
                for (int dj = 0; dj < 8; dj++)
                    acc2[qi][dj] = fmaf(aa[qi], vv[dj], acc2[qi][dj]);
        }
    }

    // row sums l -> g_l (for the normalize pass)
    __syncthreads();
#pragma unroll
    for (int j = 0; j < 8; j++) RED[(tx*8 + j)*17 + ty] = lpart[j];
    __syncthreads();
    if (tid < 128) {
        float l = 0.f;
#pragma unroll
        for (int u = 0; u < 16; u++) l += RED[tid*17 + u];
        g_l[bh*Sz + q0 + tid] = l;
    }

    // Lorentz context epilogue (1/l cancels): 8-lane shuffle reduce over d
#pragma unroll
    for (int qi = 0; qi < 4; qi++) {
        float pp = 0.f;
#pragma unroll
        for (int dj = 0; dj < 8; dj++) {
            float a = acc2[qi][dj];
            pp += ((dx == 0) && (dj == 0)) ? -a*a : a*a;
        }
#pragma unroll
        for (int off = 4; off >= 1; off >>= 1)
            pp += __shfl_xor_sync(0xffffffffu, pp, off, 8);
        float inv = rsqrtf(fmaxf(fabsf(pp), 1e-8f));
        int gq = q0 + qy*4 + qi;
        float* crow = ctx + ((size_t)((b*Sz + gq)*Hz + h)) * DPH + dx*8;
        float o[8];
#pragma unroll
        for (int dj = 0; dj < 8; dj++) o[dj] = acc2[qi][dj] * inv;
        *(float4*)(crow)     = *(float4*)(o);
        *(float4*)(crow + 4) = *(float4*)(o + 4);
    }
}

// ---------------------------------------------------------------------------
// attn normalize: lower triangle *= 1/l, upper triangle = 0.
// ---------------------------------------------------------------------------
__global__ __launch_bounds__(256) void norm_kernel(float* __restrict__ attn)
{
    const int q = blockIdx.x;
    const int bh = blockIdx.y;
    const float inv = 1.f / g_l[bh*Sz + q];
    float4* row = (float4*)(attn + (size_t)bh * Sz * Sz + (size_t)q * Sz);
    const float4 zero = make_float4(0.f, 0.f, 0.f, 0.f);
#pragma unroll
    for (int it = 0; it < 2; it++) {
        int p = threadIdx.x + it * 256;     // float4 index, 512 per row
        if (p * 4 > q) {
            row[p] = zero;
        } else {
            float4 v = row[p];               // entries past diag already 0
            v.x *= inv; v.y *= inv; v.z *= inv; v.w *= inv;
            row[p] = v;
        }
    }
}

extern "C" void kernel_launch(void* const* d_in, const int* in_sizes, int n_in,
                              void* d_out, int out_size)
{
    const float* key   = (const float*)d_in[0];
    const float* value = (const float*)d_in[1];
    const float* query = (const float*)d_in[2];
    // d_in[3] = mask (strict upper triangle), applied analytically
    const float* Wq = (const float*)d_in[4];
    const float* bq = (const float*)d_in[5];
    const float* sq = (const float*)d_in[6];
    const float* Wk = (const float*)d_in[7];
    const float* bk = (const float*)d_in[8];
    const float* sk = (const float*)d_in[9];
    const float* Wv = (const float*)d_in[10];
    const float* bv = (const float*)d_in[11];
    const float* sv = (const float*)d_in[12];
    const float* att_scale = (const float*)d_in[13];

    float* ctx  = (float*)d_out;
    float* attn = ctx + (size_t)Bz * Sz * Dz;

    dim3 gp(Dz / 128, Mrows / 128, 3);
    proj_kernel<<<gp, 256>>>(query, Wq, bq, sq, key, Wk, bk, sk, value, Wv, bv, sv);

    static const int smem_bytes = (8448 + 8704 + 16896 + 128*17) * 4;
    cudaFuncSetAttribute(attn_kernel, cudaFuncAttributeMaxDynamicSharedMemorySize, smem_bytes);
    attn_kernel<<<BHn * NQT, 256, smem_bytes>>>(attn, ctx, att_scale);

    dim3 gn(Sz, BHn);
    norm_kernel<<<gn, 256>>>(attn);
}

// round 6
// speedup vs baseline: 2.5765x; 1.6862x over previous
#include <cuda_runtime.h>
#include <cuda_bf16.h>
#include <math.h>

#define Bz 2
#define Sz 2048
#define Dz 512
#define Hz 8
#define DPH 64
#define BHn (Bz*Hz)
#define Mrows (Bz*Sz)
#define QT 128
#define NQT (Sz/QT)

__device__ float g_q[(size_t)BHn*Sz*DPH];
__device__ float g_k[(size_t)BHn*Sz*DPH];
__device__ float g_v[(size_t)BHn*Sz*DPH];
__device__ float g_l[BHn*Sz];

// ===================== helpers =====================
__device__ __forceinline__ unsigned smem_u32(const void* p) {
    unsigned a;
    asm("{ .reg .u64 t; cvta.to.shared.u64 t, %1; cvt.u32.u64 %0, t; }" : "=r"(a) : "l"(p));
    return a;
}
#define SWZ(x) ((x) ^ (((x) >> 3) & 0x70))
__device__ __forceinline__ void st2(unsigned a, unsigned x, unsigned y) {
    asm volatile("st.shared.v2.b32 [%0], {%1,%2};" :: "r"(a), "r"(x), "r"(y) : "memory");
}
__device__ __forceinline__ float tobf(float x) { return __bfloat162float(__float2bfloat16_rn(x)); }
__device__ __forceinline__ unsigned pk(float a, float b) {
    __nv_bfloat162 t = __floats2bfloat162_rn(a, b);
    return *(unsigned*)&t;
}
__device__ __forceinline__ void splitst(unsigned ahi, unsigned alo, float x, float y, float z, float w) {
    float hx = tobf(x), hy = tobf(y), hz = tobf(z), hw = tobf(w);
    st2(ahi, pk(hx, hy), pk(hz, hw));
    st2(alo, pk(x - hx, y - hy), pk(z - hz, w - hw));
}
__device__ __forceinline__ void ldsm4(unsigned addr, unsigned& r0, unsigned& r1, unsigned& r2, unsigned& r3) {
    asm volatile("ldmatrix.sync.aligned.m8n8.x4.shared.b16 {%0,%1,%2,%3}, [%4];"
        : "=r"(r0), "=r"(r1), "=r"(r2), "=r"(r3) : "r"(addr));
}
__device__ __forceinline__ void ldsm4t(unsigned addr, unsigned& r0, unsigned& r1, unsigned& r2, unsigned& r3) {
    asm volatile("ldmatrix.sync.aligned.m8n8.x4.trans.shared.b16 {%0,%1,%2,%3}, [%4];"
        : "=r"(r0), "=r"(r1), "=r"(r2), "=r"(r3) : "r"(addr));
}
__device__ __forceinline__ void mma16816(float* c, const unsigned* a, unsigned b0, unsigned b1) {
    asm volatile("mma.sync.aligned.m16n8k16.row.col.f32.bf16.bf16.f32 "
        "{%0,%1,%2,%3},{%4,%5,%6,%7},{%8,%9},{%0,%1,%2,%3};"
        : "+f"(c[0]), "+f"(c[1]), "+f"(c[2]), "+f"(c[3])
        : "r"(a[0]), "r"(a[1]), "r"(a[2]), "r"(a[3]), "r"(b0), "r"(b1));
}

#define SM_QHI 0u
#define SM_QLO 16384u
#define SM_KHI 32768u
#define SM_KLO 49152u
#define SM_VHI 65536u
#define SM_VLO 81920u
#define SM_RED 98304u
#define SMEM_DYN (98304 + 1024 + 1024)

// ---------------------------------------------------------------------------
// Fused projections (fp32): y = X@W^T+b, Lorentz epilogue. z: 0=q(qm) 1=k 2=v
// ---------------------------------------------------------------------------
__global__ __launch_bounds__(256) void proj_kernel(
    const float* __restrict__ Xq, const float* __restrict__ Wq, const float* __restrict__ bq, const float* __restrict__ sq,
    const float* __restrict__ Xk, const float* __restrict__ Wk, const float* __restrict__ bk, const float* __restrict__ sk,
    const float* __restrict__ Xv, const float* __restrict__ Wv, const float* __restrict__ bv, const float* __restrict__ sv)
{
    const int z = blockIdx.z;
    const float* X    = (z==0)?Xq:(z==1)?Xk:Xv;
    const float* W    = (z==0)?Wq:(z==1)?Wk:Wv;
    const float* bias = (z==0)?bq:(z==1)?bk:bv;
    const float* lsc  = (z==0)?sq:(z==1)?sk:sv;
    float* out = (z==0)?g_q:(z==1)?g_k:g_v;

    __shared__ float As[16*132];
    __shared__ float Bs[16*132];
    __shared__ float red[128*17];
    __shared__ float tsh[256];
    __shared__ float fsh[256];

    const int tid = threadIdx.x;
    const int tx = tid & 15, ty = tid >> 4;
    const int n0 = blockIdx.x * 128;
    const int m0 = blockIdx.y * 128;
    const int lr = tid >> 1;
    const int lh = tid & 1;

    float acc[8][8];
#pragma unroll
    for (int i = 0; i < 8; i++)
#pragma unroll
        for (int j = 0; j < 8; j++) acc[i][j] = 0.f;

    const float* Xp = X + (size_t)(m0 + lr) * Dz + lh * 8;
    const float* Wp = W + (size_t)(n0 + lr) * Dz + lh * 8;
    const int cb = lr & 7, mg = lr >> 3, kb = lh * 8;
    const int c0 = ((mg ^ (lh * 2)) << 3) + cb;
    const int c1 = ((mg ^ (lh * 2 + 1)) << 3) + cb;

    for (int k0 = 0; k0 < Dz; k0 += 16) {
        float4 a0 = *(const float4*)(Xp + k0);
        float4 a1 = *(const float4*)(Xp + k0 + 4);
        float4 b0 = *(const float4*)(Wp + k0);
        float4 b1 = *(const float4*)(Wp + k0 + 4);
        __syncthreads();
        As[(kb+0)*132+c0]=a0.x; As[(kb+1)*132+c0]=a0.y; As[(kb+2)*132+c0]=a0.z; As[(kb+3)*132+c0]=a0.w;
        As[(kb+4)*132+c1]=a1.x; As[(kb+5)*132+c1]=a1.y; As[(kb+6)*132+c1]=a1.z; As[(kb+7)*132+c1]=a1.w;
        Bs[(kb+0)*132+c0]=b0.x; Bs[(kb+1)*132+c0]=b0.y; Bs[(kb+2)*132+c0]=b0.z; Bs[(kb+3)*132+c0]=b0.w;
        Bs[(kb+4)*132+c1]=b1.x; Bs[(kb+5)*132+c1]=b1.y; Bs[(kb+6)*132+c1]=b1.z; Bs[(kb+7)*132+c1]=b1.w;
        __syncthreads();
#pragma unroll
        for (int kk = 0; kk < 16; kk++) {
            int sw = (kk >> 2) & 3;
            const float* ap = &As[kk*132 + ((ty ^ sw) << 3)];
            const float* bp = &Bs[kk*132 + ((tx ^ sw) << 3)];
            float a[8], b[8];
            *(float4*)(a)   = *(const float4*)(ap);
            *(float4*)(a+4) = *(const float4*)(ap+4);
            *(float4*)(b)   = *(const float4*)(bp);
            *(float4*)(b+4) = *(const float4*)(bp+4);
#pragma unroll
            for (int i = 0; i < 8; i++)
#pragma unroll
                for (int j = 0; j < 8; j++) acc[i][j] = fmaf(a[i], b[j], acc[i][j]);
        }
    }

    const float es = expf(lsc[0]);
    float b8[8];
#pragma unroll
    for (int j = 0; j < 8; j++) b8[j] = bias[n0 + tx*8 + j];
#pragma unroll
    for (int i = 0; i < 8; i++) {
        float ps = 0.f;
#pragma unroll
        for (int j = 0; j < 8; j++) {
            float y = acc[i][j] + b8[j];
            acc[i][j] = y;
            if ((((tx & 7) << 3) | j) != 0) ps = fmaf(y, y, ps);
        }
        red[(ty*8+i)*17 + tx] = ps;
    }
    __syncthreads();
    if ((tx & 7) == 0) {
#pragma unroll
        for (int i = 0; i < 8; i++) {
            int r = ty*8 + i;
            float sqs = 0.f;
#pragma unroll
            for (int u = 0; u < 8; u++) sqs += red[r*17 + tx + u];
            sqs = fmaxf(sqs, 1e-8f);
            float t = es / (1.f + expf(-acc[i][0])) + 1.1f;
            float f = sqrtf((t*t - 1.f) / sqs);
            tsh[r*2 + (tx>>3)] = t;
            fsh[r*2 + (tx>>3)] = f;
        }
    }
    __syncthreads();
    const int hbase = n0 >> 6;
#pragma unroll
    for (int i = 0; i < 8; i++) {
        int m = m0 + ty*8 + i;
        int bb = m >> 11, s = m & (Sz - 1);
        int ch = tx >> 3, h = hbase + ch;
        float t = tsh[(ty*8+i)*2 + ch];
        float f = fsh[(ty*8+i)*2 + ch];
        float o[8];
#pragma unroll
        for (int j = 0; j < 8; j++) {
            int lc = ((tx & 7) << 3) + j;
            o[j] = (lc == 0) ? ((z == 0) ? -t : t) : acc[i][j] * f;
        }
        float* orow = out + ((size_t)((bb*Hz + h)*Sz + s)) * DPH + (tx & 7) * 8;
        *(float4*)(orow)     = *(float4*)(o);
        *(float4*)(orow + 4) = *(float4*)(o + 4);
    }
}

// ---------------------------------------------------------------------------
// Fused causal attention on tensor cores (mma.sync bf16, 3-term compensated).
// CTA: (bh, 128-q tile), 8 warps; warp w owns q rows [w*16, w*16+16).
// ---------------------------------------------------------------------------
__global__ __launch_bounds__(256, 1) void attn_kernel(
    float* __restrict__ attn, float* __restrict__ ctx,
    const float* __restrict__ scale_ptr)
{
    extern __shared__ char smraw[];
    const unsigned sb = (smem_u32(smraw) + 1023u) & ~1023u;
    float* RED = (float*)(smraw + (sb - smem_u32(smraw)) + SM_RED);

    const int blk = blockIdx.x;
    const int bh = blk & 15;
    const int qt = (NQT - 1) - (blk >> 4);   // heavy tiles first
    const int q0 = qt * QT;
    const int b = bh >> 3, h = bh & 7;

    const int tid = threadIdx.x;
    const int w = tid >> 5, l = tid & 31;

    const float inv_as = 1.f / scale_ptr[0];
    const float* Qg = g_q + (size_t)bh * Sz * DPH;
    const float* Kg = g_k + (size_t)bh * Sz * DPH;
    const float* Vg = g_v + (size_t)bh * Sz * DPH;
    float* arow = attn + (size_t)bh * Sz * Sz;

    // ---- stage Q tile (128 x 64) -> smem bf16 hi/lo, swizzled 128B rows ----
#pragma unroll
    for (int it = 0; it < 8; it++) {
        int idx = tid + it * 256;
        int r = idx >> 4, e = (idx & 15) * 4;
        float4 v = *(const float4*)(Qg + (size_t)(q0 + r) * DPH + e);
        unsigned sw = SWZ((unsigned)(r * 128 + e * 2));
        splitst(sb + SM_QHI + sw, sb + SM_QLO + sw, v.x, v.y, v.z, v.w);
    }
    __syncthreads();

    // ---- per-warp Q fragments (held across whole kernel) ----
    unsigned qh[4][4], ql[4][4];
    {
        unsigned qrow = (unsigned)(w * 16 + (l & 15));
        unsigned qoff = qrow * 128 + ((l >> 4) * 16);
#pragma unroll
        for (int c = 0; c < 4; c++) {
            unsigned sw = SWZ(qoff + c * 32);
            ldsm4(sb + SM_QHI + sw, qh[c][0], qh[c][1], qh[c][2], qh[c][3]);
            ldsm4(sb + SM_QLO + sw, ql[c][0], ql[c][1], ql[c][2], ql[c][3]);
        }
    }

    // lane patterns for B-frag ldmatrix
    const unsigned krow = (l & 7) + ((l & 16) >> 1);       // row within 16 (K frags)
    const unsigned kchalf = ((l >> 3) & 1) * 16;           // byte half (K frags)
    const unsigned vt = l >> 3;
    const unsigned vrow = (l & 7) + ((vt & 1) << 3);       // k-row within 16 (V frags)
    const unsigned vd8 = (vt >> 1) * 16;                   // byte d-half (V frags)

    float cc[8][4];
#pragma unroll
    for (int i = 0; i < 8; i++)
#pragma unroll
        for (int j = 0; j < 4; j++) cc[i][j] = 0.f;
    float lsum0 = 0.f, lsum1 = 0.f;

    const int row0 = w * 16 + (l >> 2);
    const int gq0 = q0 + row0, gq1 = gq0 + 8;
    const int colq = (l & 3) * 2;

    for (int kt = 0; kt <= qt; ++kt) {
        const int k0 = kt * QT;
        __syncthreads();   // prior iteration done with K/V smem
        // K, V tiles -> smem bf16 hi/lo
#pragma unroll
        for (int it = 0; it < 8; it++) {
            int idx = tid + it * 256;
            int r = idx >> 4, e = (idx & 15) * 4;
            unsigned sw = SWZ((unsigned)(r * 128 + e * 2));
            float4 kv = *(const float4*)(Kg + (size_t)(k0 + r) * DPH + e);
            splitst(sb + SM_KHI + sw, sb + SM_KLO + sw, kv.x, kv.y, kv.z, kv.w);
            float4 vv = *(const float4*)(Vg + (size_t)(k0 + r) * DPH + e);
            splitst(sb + SM_VHI + sw, sb + SM_VLO + sw, vv.x, vv.y, vv.z, vv.w);
        }
        __syncthreads();

        // ---- S = Q K^T (16 n8-tiles per warp) ----
        float sc[16][4];
#pragma unroll
        for (int i = 0; i < 16; i++)
#pragma unroll
            for (int j = 0; j < 4; j++) sc[i][j] = 0.f;
#pragma unroll
        for (int g = 0; g < 8; g++) {
            unsigned goff = (unsigned)(g * 16 + krow) * 128 + kchalf;
#pragma unroll
            for (int c = 0; c < 4; c++) {
                unsigned b0, b1, b2, b3, e0, e1, e2, e3;
                unsigned sw = SWZ(goff + c * 32);
                ldsm4(sb + SM_KHI + sw, b0, b1, b2, b3);
                ldsm4(sb + SM_KLO + sw, e0, e1, e2, e3);
                mma16816(sc[2*g],   qh[c], b0, b1);
                mma16816(sc[2*g+1], qh[c], b2, b3);
                mma16816(sc[2*g],   ql[c], b0, b1);
                mma16816(sc[2*g+1], ql[c], b2, b3);
                mma16816(sc[2*g],   qh[c], e0, e1);
                mma16816(sc[2*g+1], qh[c], e2, e3);
            }
        }

        // ---- exp + mask + raw P -> gmem + row-sum partials ----
        const bool diag = (kt == qt);
        float* p0 = arow + (size_t)gq0 * Sz + k0 + colq;
        float* p1 = arow + (size_t)gq1 * Sz + k0 + colq;
#pragma unroll
        for (int t = 0; t < 16; t++) {
            int gk = k0 + t * 8 + colq;
            float v0 = __expf((2.f * sc[t][0] + 2.f) * inv_as);
            float v1 = __expf((2.f * sc[t][1] + 2.f) * inv_as);
            float v2 = __expf((2.f * sc[t][2] + 2.f) * inv_as);
            float v3 = __expf((2.f * sc[t][3] + 2.f) * inv_as);
            if (diag) {
                if (gk > gq0)     v0 = 0.f;
                if (gk + 1 > gq0) v1 = 0.f;
                if (gk > gq1)     v2 = 0.f;
                if (gk + 1 > gq1) v3 = 0.f;
            }
            sc[t][0] = v0; sc[t][1] = v1; sc[t][2] = v2; sc[t][3] = v3;
            lsum0 += v0 + v1;
            lsum1 += v2 + v3;
            *(float2*)(p0 + t*8) = make_float2(v0, v1);
            *(float2*)(p1 + t*8) = make_float2(v2, v3);
        }

        // ---- ctx += P V : A-frags packed from sc, B-frags ldmatrix.trans(V) ----
#pragma unroll
        for (int kc = 0; kc < 8; kc++) {
            unsigned ah[4], al[4];
            {
                float x0 = sc[2*kc][0], x1 = sc[2*kc][1], x2 = sc[2*kc][2], x3 = sc[2*kc][3];
                float y0 = sc[2*kc+1][0], y1 = sc[2*kc+1][1], y2 = sc[2*kc+1][2], y3 = sc[2*kc+1][3];
                float hx0 = tobf(x0), hx1 = tobf(x1), hx2 = tobf(x2), hx3 = tobf(x3);
                float hy0 = tobf(y0), hy1 = tobf(y1), hy2 = tobf(y2), hy3 = tobf(y3);
                ah[0] = pk(hx0, hx1); ah[1] = pk(hx2, hx3);
                ah[2] = pk(hy0, hy1); ah[3] = pk(hy2, hy3);
                al[0] = pk(x0 - hx0, x1 - hx1); al[1] = pk(x2 - hx2, x3 - hx3);
                al[2] = pk(y0 - hy0, y1 - hy1); al[3] = pk(y2 - hy2, y3 - hy3);
            }
            unsigned koff = (unsigned)(kc * 16 + vrow) * 128 + vd8;
#pragma unroll
            for (int g = 0; g < 4; g++) {
                unsigned b0, b1, b2, b3, e0, e1, e2, e3;
                unsigned sw = SWZ(koff + g * 32);
                ldsm4t(sb + SM_VHI + sw, b0, b1, b2, b3);
                ldsm4t(sb + SM_VLO + sw, e0, e1, e2, e3);
                mma16816(cc[2*g],   ah, b0, b1);
                mma16816(cc[2*g+1], ah, b2, b3);
                mma16816(cc[2*g],   al, b0, b1);
                mma16816(cc[2*g+1], al, b2, b3);
                mma16816(cc[2*g],   ah, e0, e1);
                mma16816(cc[2*g+1], ah, e2, e3);
            }
        }
    }

    // ---- row sums l (quad reduce) ----
    lsum0 += __shfl_xor_sync(0xffffffffu, lsum0, 1);
    lsum0 += __shfl_xor_sync(0xffffffffu, lsum0, 2);
    lsum1 += __shfl_xor_sync(0xffffffffu, lsum1, 1);
    lsum1 += __shfl_xor_sync(0xffffffffu, lsum1, 2);
    if ((l & 3) == 0) {
        g_l[bh*Sz + gq0] = lsum0;
        g_l[bh*Sz + gq1] = lsum1;
    }

    // ---- Lorentz context epilogue (1/l cancels) ----
    float pp0 = 0.f, pp1 = 0.f;
#pragma unroll
    for (int t = 0; t < 8; t++) {
        float a0 = cc[t][0], a1 = cc[t][1], a2 = cc[t][2], a3 = cc[t][3];
        float s0 = (t == 0 && (l & 3) == 0) ? -a0*a0 : a0*a0;
        float s2 = (t == 0 && (l & 3) == 0) ? -a2*a2 : a2*a2;
        pp0 += s0 + a1*a1;
        pp1 += s2 + a3*a3;
    }
    pp0 += __shfl_xor_sync(0xffffffffu, pp0, 1);
    pp0 += __shfl_xor_sync(0xffffffffu, pp0, 2);
    pp1 += __shfl_xor_sync(0xffffffffu, pp1, 1);
    pp1 += __shfl_xor_sync(0xffffffffu, pp1, 2);
    float inv0 = rsqrtf(fmaxf(fabsf(pp0), 1e-8f));
    float inv1 = rsqrtf(fmaxf(fabsf(pp1), 1e-8f));
    float* c0p = ctx + ((size_t)((b*Sz + gq0)*Hz + h)) * DPH + colq;
    float* c1p = ctx + ((size_t)((b*Sz + gq1)*Hz + h)) * DPH + colq;
#pragma unroll
    for (int t = 0; t < 8; t++) {
        *(float2*)(c0p + t*8) = make_float2(cc[t][0]*inv0, cc[t][1]*inv0);
        *(float2*)(c1p + t*8) = make_float2(cc[t][2]*inv1, cc[t][3]*inv1);
    }
}

// ---------------------------------------------------------------------------
// attn normalize: lower triangle *= 1/l, upper triangle = 0.
// ---------------------------------------------------------------------------
__global__ __launch_bounds__(256) void norm_kernel(float* __restrict__ attn)
{
    const int q = blockIdx.x;
    const int bh = blockIdx.y;
    const float inv = 1.f / g_l[bh*Sz + q];
    float4* row = (float4*)(attn + (size_t)bh * Sz * Sz + (size_t)q * Sz);
    const float4 zero = make_float4(0.f, 0.f, 0.f, 0.f);
#pragma unroll
    for (int it = 0; it < 2; it++) {
        int p = threadIdx.x + it * 256;
        if (p * 4 > q) {
            row[p] = zero;
        } else {
            float4 v = row[p];
            v.x *= inv; v.y *= inv; v.z *= inv; v.w *= inv;
            row[p] = v;
        }
    }
}

extern "C" void kernel_launch(void* const* d_in, const int* in_sizes, int n_in,
                              void* d_out, int out_size)
{
    const float* key   = (const float*)d_in[0];
    const float* value = (const float*)d_in[1];
    const float* query = (const float*)d_in[2];
    const float* Wq = (const float*)d_in[4];
    const float* bq = (const float*)d_in[5];
    const float* sq = (const float*)d_in[6];
    const float* Wk = (const float*)d_in[7];
    const float* bk = (const float*)d_in[8];
    const float* sk = (const float*)d_in[9];
    const float* Wv = (const float*)d_in[10];
    const float* bv = (const float*)d_in[11];
    const float* sv = (const float*)d_in[12];
    const float* att_scale = (const float*)d_in[13];

    float* ctx  = (float*)d_out;
    float* attn = ctx + (size_t)Bz * Sz * Dz;

    dim3 gp(Dz / 128, Mrows / 128, 3);
    proj_kernel<<<gp, 256>>>(query, Wq, bq, sq, key, Wk, bk, sk, value, Wv, bv, sv);

    cudaFuncSetAttribute(attn_kernel, cudaFuncAttributeMaxDynamicSharedMemorySize, SMEM_DYN);
    attn_kernel<<<BHn * NQT, 256, SMEM_DYN>>>(attn, ctx, att_scale);

    dim3 gn(Sz, BHn);
    norm_kernel<<<gn, 256>>>(attn);
}

// round 7
// speedup vs baseline: 3.5057x; 1.3606x over previous
#include <cuda_runtime.h>
#include <cuda_bf16.h>
#include <math.h>

#define Bz 2
#define Sz 2048
#define Dz 512
#define Hz 8
#define DPH 64
#define BHn (Bz*Hz)
#define Mrows (Bz*Sz)
#define QT 128
#define NQT (Sz/QT)

__device__ float g_q[(size_t)BHn*Sz*DPH];
__device__ float g_k[(size_t)BHn*Sz*DPH];
__device__ float g_v[(size_t)BHn*Sz*DPH];
__device__ float g_l[BHn*Sz];

// ===================== helpers =====================
__device__ __forceinline__ unsigned smem_u32(const void* p) {
    unsigned a;
    asm("{ .reg .u64 t; cvta.to.shared.u64 t, %1; cvt.u32.u64 %0, t; }" : "=r"(a) : "l"(p));
    return a;
}
#define SWZ(x) ((x) ^ (((x) >> 3) & 0x70))
__device__ __forceinline__ void st2(unsigned a, unsigned x, unsigned y) {
    asm volatile("st.shared.v2.b32 [%0], {%1,%2};" :: "r"(a), "r"(x), "r"(y) : "memory");
}
__device__ __forceinline__ float tobf(float x) { return __bfloat162float(__float2bfloat16_rn(x)); }
__device__ __forceinline__ unsigned pk(float a, float b) {
    __nv_bfloat162 t = __floats2bfloat162_rn(a, b);
    return *(unsigned*)&t;
}
__device__ __forceinline__ void splitst(unsigned ahi, unsigned alo, float x, float y, float z, float w) {
    float hx = tobf(x), hy = tobf(y), hz = tobf(z), hw = tobf(w);
    st2(ahi, pk(hx, hy), pk(hz, hw));
    st2(alo, pk(x - hx, y - hy), pk(z - hz, w - hw));
}
__device__ __forceinline__ void ldsm4(unsigned addr, unsigned& r0, unsigned& r1, unsigned& r2, unsigned& r3) {
    asm volatile("ldmatrix.sync.aligned.m8n8.x4.shared.b16 {%0,%1,%2,%3}, [%4];"
        : "=r"(r0), "=r"(r1), "=r"(r2), "=r"(r3) : "r"(addr));
}
__device__ __forceinline__ void ldsm4t(unsigned addr, unsigned& r0, unsigned& r1, unsigned& r2, unsigned& r3) {
    asm volatile("ldmatrix.sync.aligned.m8n8.x4.trans.shared.b16 {%0,%1,%2,%3}, [%4];"
        : "=r"(r0), "=r"(r1), "=r"(r2), "=r"(r3) : "r"(addr));
}
__device__ __forceinline__ void mma16816(float* c, const unsigned* a, unsigned b0, unsigned b1) {
    asm volatile("mma.sync.aligned.m16n8k16.row.col.f32.bf16.bf16.f32 "
        "{%0,%1,%2,%3},{%4,%5,%6,%7},{%8,%9},{%0,%1,%2,%3};"
        : "+f"(c[0]), "+f"(c[1]), "+f"(c[2]), "+f"(c[3])
        : "r"(a[0]), "r"(a[1]), "r"(a[2]), "r"(a[3]), "r"(b0), "r"(b1));
}

// attn smem offsets
#define SM_QHI 0u
#define SM_QLO 16384u
#define SM_KHI 32768u
#define SM_KLO 49152u
#define SM_VHI 65536u
#define SM_VLO 81920u
#define SMEM_DYN (98304 + 2048)
// proj smem offsets
#define PM_XHI 0u
#define PM_XLO 16384u
#define PM_WHI 32768u
#define PM_WLO 49152u
#define SMEM_PROJ (65536 + 1024)

// ---------------------------------------------------------------------------
// Projections on tensor cores: y = X@W^T + b (compensated bf16), Lorentz
// epilogue. CTA = 128 M-rows x 128 N-cols; 8 warps x 16 rows.
// z: 0=q(store qm) 1=k 2=v
// ---------------------------------------------------------------------------
__global__ __launch_bounds__(256, 1) void proj_kernel(
    const float* __restrict__ Xq, const float* __restrict__ Wq, const float* __restrict__ bq, const float* __restrict__ sq,
    const float* __restrict__ Xk, const float* __restrict__ Wk, const float* __restrict__ bk, const float* __restrict__ sk,
    const float* __restrict__ Xv, const float* __restrict__ Wv, const float* __restrict__ bv, const float* __restrict__ sv)
{
    const int z = blockIdx.z;
    const float* X    = (z==0)?Xq:(z==1)?Xk:Xv;
    const float* W    = (z==0)?Wq:(z==1)?Wk:Wv;
    const float* bias = (z==0)?bq:(z==1)?bk:bv;
    const float* lsc  = (z==0)?sq:(z==1)?sk:sv;
    float* out = (z==0)?g_q:(z==1)?g_k:g_v;

    extern __shared__ char smraw[];
    const unsigned sb = (smem_u32(smraw) + 1023u) & ~1023u;

    const int tid = threadIdx.x;
    const int w = tid >> 5, l = tid & 31;
    const int n0 = blockIdx.x * 128;
    const int m0 = blockIdx.y * 128;

    float cc[16][4];
#pragma unroll
    for (int i = 0; i < 16; i++)
#pragma unroll
        for (int j = 0; j < 4; j++) cc[i][j] = 0.f;

    const unsigned krow = (l & 7) + ((l & 16) >> 1);
    const unsigned kchalf = ((l >> 3) & 1) * 16;
    const unsigned qoff = (unsigned)(w * 16 + (l & 15)) * 128 + ((l >> 4) * 16);

    for (int k0 = 0; k0 < Dz; k0 += 64) {
        __syncthreads();
#pragma unroll
        for (int it = 0; it < 8; it++) {
            int idx = tid + it * 256;
            int r = idx >> 4, e = (idx & 15) * 4;
            unsigned sw = SWZ((unsigned)(r * 128 + e * 2));
            float4 xv = *(const float4*)(X + (size_t)(m0 + r) * Dz + k0 + e);
            splitst(sb + PM_XHI + sw, sb + PM_XLO + sw, xv.x, xv.y, xv.z, xv.w);
            float4 wv = *(const float4*)(W + (size_t)(n0 + r) * Dz + k0 + e);
            splitst(sb + PM_WHI + sw, sb + PM_WLO + sw, wv.x, wv.y, wv.z, wv.w);
        }
        __syncthreads();

        unsigned ah[4][4], al[4][4];
#pragma unroll
        for (int c = 0; c < 4; c++) {
            unsigned sw = SWZ(qoff + c * 32);
            ldsm4(sb + PM_XHI + sw, ah[c][0], ah[c][1], ah[c][2], ah[c][3]);
            ldsm4(sb + PM_XLO + sw, al[c][0], al[c][1], al[c][2], al[c][3]);
        }
#pragma unroll
        for (int g = 0; g < 8; g++) {
            unsigned goff = (unsigned)(g * 16 + krow) * 128 + kchalf;
#pragma unroll
            for (int c = 0; c < 4; c++) {
                unsigned b0, b1, b2, b3, e0, e1, e2, e3;
                unsigned sw = SWZ(goff + c * 32);
                ldsm4(sb + PM_WHI + sw, b0, b1, b2, b3);
                ldsm4(sb + PM_WLO + sw, e0, e1, e2, e3);
                mma16816(cc[2*g],   ah[c], b0, b1);
                mma16816(cc[2*g+1], ah[c], b2, b3);
                mma16816(cc[2*g],   al[c], b0, b1);
                mma16816(cc[2*g+1], al[c], b2, b3);
                mma16816(cc[2*g],   ah[c], e0, e1);
                mma16816(cc[2*g+1], ah[c], e2, e3);
            }
        }
    }

    // ---- epilogue: bias + per-head Lorentz projection ----
    const float es = expf(lsc[0]);
    const int colq = (l & 3) * 2;
    const int r0 = m0 + w * 16 + (l >> 2);   // global row (gq0); gq1 = +8
    const int hbase = n0 >> 6;

#pragma unroll
    for (int t = 0; t < 16; t++) {
        float bv0 = bias[n0 + t*8 + colq];
        float bv1 = bias[n0 + t*8 + colq + 1];
        cc[t][0] += bv0; cc[t][1] += bv1;
        cc[t][2] += bv0; cc[t][3] += bv1;
    }

#pragma unroll
    for (int g2 = 0; g2 < 2; g2++) {   // head within this warp's 128 cols
        float pp0 = 0.f, pp1 = 0.f;
#pragma unroll
        for (int tt = 0; tt < 8; tt++) {
            int t = g2 * 8 + tt;
            bool istime = (colq == 0) && (tt == 0);   // local col 0
            float y00 = cc[t][0], y01 = cc[t][1], y10 = cc[t][2], y11 = cc[t][3];
            pp0 += (istime ? 0.f : y00*y00) + y01*y01;
            pp1 += (istime ? 0.f : y10*y10) + y11*y11;
        }
        pp0 += __shfl_xor_sync(0xffffffffu, pp0, 1);
        pp0 += __shfl_xor_sync(0xffffffffu, pp0, 2);
        pp1 += __shfl_xor_sync(0xffffffffu, pp1, 1);
        pp1 += __shfl_xor_sync(0xffffffffu, pp1, 2);
        float t0 = 0.f, t1 = 0.f, f0 = 0.f, f1 = 0.f;
        if ((l & 3) == 0) {
            float y0a = cc[g2*8][0];   // time raw, row gq0
            float y0b = cc[g2*8][2];   // time raw, row gq1
            t0 = es / (1.f + expf(-y0a)) + 1.1f;
            t1 = es / (1.f + expf(-y0b)) + 1.1f;
            f0 = sqrtf((t0*t0 - 1.f) / fmaxf(pp0, 1e-8f));
            f1 = sqrtf((t1*t1 - 1.f) / fmaxf(pp1, 1e-8f));
        }
        int src = l & ~3;
        t0 = __shfl_sync(0xffffffffu, t0, src);
        t1 = __shfl_sync(0xffffffffu, t1, src);
        f0 = __shfl_sync(0xffffffffu, f0, src);
        f1 = __shfl_sync(0xffffffffu, f1, src);

        int h = hbase + g2;
        int bb0 = r0 >> 11, s0 = r0 & (Sz - 1);
        int r1 = r0 + 8;
        int bb1 = r1 >> 11, s1 = r1 & (Sz - 1);
        float* o0 = out + ((size_t)((bb0*Hz + h)*Sz + s0)) * DPH;
        float* o1 = out + ((size_t)((bb1*Hz + h)*Sz + s1)) * DPH;
#pragma unroll
        for (int tt = 0; tt < 8; tt++) {
            int t = g2 * 8 + tt;
            int lc = tt * 8 + colq;
            bool istime = (lc == 0);
            float v00 = istime ? ((z == 0) ? -t0 : t0) : cc[t][0] * f0;
            float v01 = cc[t][1] * f0;
            float v10 = istime ? ((z == 0) ? -t1 : t1) : cc[t][2] * f1;
            float v11 = cc[t][3] * f1;
            *(float2*)(o0 + lc) = make_float2(v00, v01);
            *(float2*)(o1 + lc) = make_float2(v10, v11);
        }
    }
}

// ---------------------------------------------------------------------------
// Fused causal attention on tensor cores (mma.sync bf16, 3-term compensated).
// ---------------------------------------------------------------------------
__global__ __launch_bounds__(256, 1) void attn_kernel(
    float* __restrict__ attn, float* __restrict__ ctx,
    const float* __restrict__ scale_ptr)
{
    extern __shared__ char smraw[];
    const unsigned sb = (smem_u32(smraw) + 1023u) & ~1023u;

    const int blk = blockIdx.x;
    const int bh = blk & 15;
    const int qt = (NQT - 1) - (blk >> 4);
    const int q0 = qt * QT;
    const int b = bh >> 3, h = bh & 7;

    const int tid = threadIdx.x;
    const int w = tid >> 5, l = tid & 31;

    const float inv_as = 1.f / scale_ptr[0];
    const float* Qg = g_q + (size_t)bh * Sz * DPH;
    const float* Kg = g_k + (size_t)bh * Sz * DPH;
    const float* Vg = g_v + (size_t)bh * Sz * DPH;
    float* arow = attn + (size_t)bh * Sz * Sz;

#pragma unroll
    for (int it = 0; it < 8; it++) {
        int idx = tid + it * 256;
        int r = idx >> 4, e = (idx & 15) * 4;
        float4 v = *(const float4*)(Qg + (size_t)(q0 + r) * DPH + e);
        unsigned sw = SWZ((unsigned)(r * 128 + e * 2));
        splitst(sb + SM_QHI + sw, sb + SM_QLO + sw, v.x, v.y, v.z, v.w);
    }
    __syncthreads();

    unsigned qh[4][4], ql[4][4];
    {
        unsigned qoff = (unsigned)(w * 16 + (l & 15)) * 128 + ((l >> 4) * 16);
#pragma unroll
        for (int c = 0; c < 4; c++) {
            unsigned sw = SWZ(qoff + c * 32);
            ldsm4(sb + SM_QHI + sw, qh[c][0], qh[c][1], qh[c][2], qh[c][3]);
            ldsm4(sb + SM_QLO + sw, ql[c][0], ql[c][1], ql[c][2], ql[c][3]);
        }
    }

    const unsigned krow = (l & 7) + ((l & 16) >> 1);
    const unsigned kchalf = ((l >> 3) & 1) * 16;
    const unsigned vt = l >> 3;
    const unsigned vrow = (l & 7) + ((vt & 1) << 3);
    const unsigned vd8 = (vt >> 1) * 16;

    float cc[8][4];
#pragma unroll
    for (int i = 0; i < 8; i++)
#pragma unroll
        for (int j = 0; j < 4; j++) cc[i][j] = 0.f;
    float lsum0 = 0.f, lsum1 = 0.f;

    const int row0 = w * 16 + (l >> 2);
    const int gq0 = q0 + row0, gq1 = gq0 + 8;
    const int colq = (l & 3) * 2;

    for (int kt = 0; kt <= qt; ++kt) {
        const int k0 = kt * QT;
        __syncthreads();
#pragma unroll
        for (int it = 0; it < 8; it++) {
            int idx = tid + it * 256;
            int r = idx >> 4, e = (idx & 15) * 4;
            unsigned sw = SWZ((unsigned)(r * 128 + e * 2));
            float4 kv = *(const float4*)(Kg + (size_t)(k0 + r) * DPH + e);
            splitst(sb + SM_KHI + sw, sb + SM_KLO + sw, kv.x, kv.y, kv.z, kv.w);
            float4 vv = *(const float4*)(Vg + (size_t)(k0 + r) * DPH + e);
            splitst(sb + SM_VHI + sw, sb + SM_VLO + sw, vv.x, vv.y, vv.z, vv.w);
        }
        __syncthreads();

        float sc[16][4];
#pragma unroll
        for (int i = 0; i < 16; i++)
#pragma unroll
            for (int j = 0; j < 4; j++) sc[i][j] = 0.f;
#pragma unroll
        for (int g = 0; g < 8; g++) {
            unsigned goff = (unsigned)(g * 16 + krow) * 128 + kchalf;
#pragma unroll
            for (int c = 0; c < 4; c++) {
                unsigned b0, b1, b2, b3, e0, e1, e2, e3;
                unsigned sw = SWZ(goff + c * 32);
                ldsm4(sb + SM_KHI + sw, b0, b1, b2, b3);
                ldsm4(sb + SM_KLO + sw, e0, e1, e2, e3);
                mma16816(sc[2*g],   qh[c], b0, b1);
                mma16816(sc[2*g+1], qh[c], b2, b3);
                mma16816(sc[2*g],   ql[c], b0, b1);
                mma16816(sc[2*g+1], ql[c], b2, b3);
                mma16816(sc[2*g],   qh[c], e0, e1);
                mma16816(sc[2*g+1], qh[c], e2, e3);
            }
        }

        const bool diag = (kt == qt);
        float* p0 = arow + (size_t)gq0 * Sz + k0 + colq;
        float* p1 = arow + (size_t)gq1 * Sz + k0 + colq;
#pragma unroll
        for (int t = 0; t < 16; t++) {
            int gk = k0 + t * 8 + colq;
            float v0 = __expf((2.f * sc[t][0] + 2.f) * inv_as);
            float v1 = __expf((2.f * sc[t][1] + 2.f) * inv_as);
            float v2 = __expf((2.f * sc[t][2] + 2.f) * inv_as);
            float v3 = __expf((2.f * sc[t][3] + 2.f) * inv_as);
            if (diag) {
                if (gk > gq0)     v0 = 0.f;
                if (gk + 1 > gq0) v1 = 0.f;
                if (gk > gq1)     v2 = 0.f;
                if (gk + 1 > gq1) v3 = 0.f;
            }
            sc[t][0] = v0; sc[t][1] = v1; sc[t][2] = v2; sc[t][3] = v3;
            lsum0 += v0 + v1;
            lsum1 += v2 + v3;
            *(float2*)(p0 + t*8) = make_float2(v0, v1);
            *(float2*)(p1 + t*8) = make_float2(v2, v3);
        }

#pragma unroll
        for (int kc = 0; kc < 8; kc++) {
            unsigned ah[4], al[4];
            {
                float x0 = sc[2*kc][0], x1 = sc[2*kc][1], x2 = sc[2*kc][2], x3 = sc[2*kc][3];
                float y0 = sc[2*kc+1][0], y1 = sc[2*kc+1][1], y2 = sc[2*kc+1][2], y3 = sc[2*kc+1][3];
                float hx0 = tobf(x0), hx1 = tobf(x1), hx2 = tobf(x2), hx3 = tobf(x3);
                float hy0 = tobf(y0), hy1 = tobf(y1), hy2 = tobf(y2), hy3 = tobf(y3);
                ah[0] = pk(hx0, hx1); ah[1] = pk(hx2, hx3);
                ah[2] = pk(hy0, hy1); ah[3] = pk(hy2, hy3);
                al[0] = pk(x0 - hx0, x1 - hx1); al[1] = pk(x2 - hx2, x3 - hx3);
                al[2] = pk(y0 - hy0, y1 - hy1); al[3] = pk(y2 - hy2, y3 - hy3);
            }
            unsigned koff = (unsigned)(kc * 16 + vrow) * 128 + vd8;
#pragma unroll
            for (int g = 0; g < 4; g++) {
                unsigned b0, b1, b2, b3, e0, e1, e2, e3;
                unsigned sw = SWZ(koff + g * 32);
                ldsm4t(sb + SM_VHI + sw, b0, b1, b2, b3);
                ldsm4t(sb + SM_VLO + sw, e0, e1, e2, e3);
                mma16816(cc[2*g],   ah, b0, b1);
                mma16816(cc[2*g+1], ah, b2, b3);
                mma16816(cc[2*g],   al, b0, b1);
                mma16816(cc[2*g+1], al, b2, b3);
                mma16816(cc[2*g],   ah, e0, e1);
                mma16816(cc[2*g+1], ah, e2, e3);
            }
        }
    }

    lsum0 += __shfl_xor_sync(0xffffffffu, lsum0, 1);
    lsum0 += __shfl_xor_sync(0xffffffffu, lsum0, 2);
    lsum1 += __shfl_xor_sync(0xffffffffu, lsum1, 1);
    lsum1 += __shfl_xor_sync(0xffffffffu, lsum1, 2);
    if ((l & 3) == 0) {
        g_l[bh*Sz + gq0] = lsum0;
        g_l[bh*Sz + gq1] = lsum1;
    }

    float pp0 = 0.f, pp1 = 0.f;
#pragma unroll
    for (int t = 0; t < 8; t++) {
        float a0 = cc[t][0], a1 = cc[t][1], a2 = cc[t][2], a3 = cc[t][3];
        float s0 = (t == 0 && (l & 3) == 0) ? -a0*a0 : a0*a0;
        float s2 = (t == 0 && (l & 3) == 0) ? -a2*a2 : a2*a2;
        pp0 += s0 + a1*a1;
        pp1 += s2 + a3*a3;
    }
    pp0 += __shfl_xor_sync(0xffffffffu, pp0, 1);
    pp0 += __shfl_xor_sync(0xffffffffu, pp0, 2);
    pp1 += __shfl_xor_sync(0xffffffffu, pp1, 1);
    pp1 += __shfl_xor_sync(0xffffffffu, pp1, 2);
    float inv0 = rsqrtf(fmaxf(fabsf(pp0), 1e-8f));
    float inv1 = rsqrtf(fmaxf(fabsf(pp1), 1e-8f));
    float* c0p = ctx + ((size_t)((b*Sz + gq0)*Hz + h)) * DPH + colq;
    float* c1p = ctx + ((size_t)((b*Sz + gq1)*Hz + h)) * DPH + colq;
#pragma unroll
    for (int t = 0; t < 8; t++) {
        *(float2*)(c0p + t*8) = make_float2(cc[t][0]*inv0, cc[t][1]*inv0);
        *(float2*)(c1p + t*8) = make_float2(cc[t][2]*inv1, cc[t][3]*inv1);
    }
}

// ---------------------------------------------------------------------------
__global__ __launch_bounds__(256) void norm_kernel(float* __restrict__ attn)
{
    const int q = blockIdx.x;
    const int bh = blockIdx.y;
    const float inv = 1.f / g_l[bh*Sz + q];
    float4* row = (float4*)(attn + (size_t)bh * Sz * Sz + (size_t)q * Sz);
    const float4 zero = make_float4(0.f, 0.f, 0.f, 0.f);
#pragma unroll
    for (int it = 0; it < 2; it++) {
        int p = threadIdx.x + it * 256;
        if (p * 4 > q) {
            row[p] = zero;
        } else {
            float4 v = row[p];
            v.x *= inv; v.y *= inv; v.z *= inv; v.w *= inv;
            row[p] = v;
        }
    }
}

extern "C" void kernel_launch(void* const* d_in, const int* in_sizes, int n_in,
                              void* d_out, int out_size)
{
    const float* key   = (const float*)d_in[0];
    const float* value = (const float*)d_in[1];
    const float* query = (const float*)d_in[2];
    const float* Wq = (const float*)d_in[4];
    const float* bq = (const float*)d_in[5];
    const float* sq = (const float*)d_in[6];
    const float* Wk = (const float*)d_in[7];
    const float* bk = (const float*)d_in[8];
    const float* sk = (const float*)d_in[9];
    const float* Wv = (const float*)d_in[10];
    const float* bv = (const float*)d_in[11];
    const float* sv = (const float*)d_in[12];
    const float* att_scale = (const float*)d_in[13];

    float* ctx  = (float*)d_out;
    float* attn = ctx + (size_t)Bz * Sz * Dz;

    cudaFuncSetAttribute(proj_kernel, cudaFuncAttributeMaxDynamicSharedMemorySize, SMEM_PROJ);
    dim3 gp(Dz / 128, Mrows / 128, 3);
    proj_kernel<<<gp, 256, SMEM_PROJ>>>(query, Wq, bq, sq, key, Wk, bk, sk, value, Wv, bv, sv);

    cudaFuncSetAttribute(attn_kernel, cudaFuncAttributeMaxDynamicSharedMemorySize, SMEM_DYN);
    attn_kernel<<<BHn * NQT, 256, SMEM_DYN>>>(attn, ctx, att_scale);

    dim3 gn(Sz, BHn);
    norm_kernel<<<gn, 256>>>(attn);
}

// round 8
// speedup vs baseline: 3.8187x; 1.0893x over previous
#include <cuda_runtime.h>
#include <cuda_bf16.h>
#include <math.h>

#define Bz 2
#define Sz 2048
#define Dz 512
#define Hz 8
#define DPH 64
#define BHn (Bz*Hz)
#define Mrows (Bz*Sz)
#define QT 128
#define NQT (Sz/QT)
#define NX ((size_t)Mrows*Dz)
#define NW ((size_t)Dz*Dz)

__device__ __nv_bfloat16 gXhi[3][NX];
__device__ __nv_bfloat16 gXlo[3][NX];
__device__ __nv_bfloat16 gWhi[3][NW];
__device__ __nv_bfloat16 gWlo[3][NW];
__device__ __nv_bfloat16 gPhi[3][(size_t)BHn*Sz*DPH];   // q,k,v projected hi
__device__ __nv_bfloat16 gPlo[3][(size_t)BHn*Sz*DPH];   // q,k,v projected lo
__device__ float g_l[BHn*Sz];

// ===================== helpers =====================
__device__ __forceinline__ unsigned smem_u32(const void* p) {
    unsigned a;
    asm("{ .reg .u64 t; cvta.to.shared.u64 t, %1; cvt.u32.u64 %0, t; }" : "=r"(a) : "l"(p));
    return a;
}
#define SWZ(x) ((x) ^ (((x) >> 3) & 0x70))
__device__ __forceinline__ float tobf(float x) { return __bfloat162float(__float2bfloat16_rn(x)); }
__device__ __forceinline__ unsigned pk(float a, float b) {
    __nv_bfloat162 t = __floats2bfloat162_rn(a, b);
    return *(unsigned*)&t;
}
__device__ __forceinline__ void ldsm4(unsigned addr, unsigned& r0, unsigned& r1, unsigned& r2, unsigned& r3) {
    asm volatile("ldmatrix.sync.aligned.m8n8.x4.shared.b16 {%0,%1,%2,%3}, [%4];"
        : "=r"(r0), "=r"(r1), "=r"(r2), "=r"(r3) : "r"(addr));
}
__device__ __forceinline__ void ldsm4t(unsigned addr, unsigned& r0, unsigned& r1, unsigned& r2, unsigned& r3) {
    asm volatile("ldmatrix.sync.aligned.m8n8.x4.trans.shared.b16 {%0,%1,%2,%3}, [%4];"
        : "=r"(r0), "=r"(r1), "=r"(r2), "=r"(r3) : "r"(addr));
}
__device__ __forceinline__ void mma16816(float* c, const unsigned* a, unsigned b0, unsigned b1) {
    asm volatile("mma.sync.aligned.m16n8k16.row.col.f32.bf16.bf16.f32 "
        "{%0,%1,%2,%3},{%4,%5,%6,%7},{%8,%9},{%0,%1,%2,%3};"
        : "+f"(c[0]), "+f"(c[1]), "+f"(c[2]), "+f"(c[3])
        : "r"(a[0]), "r"(a[1]), "r"(a[2]), "r"(a[3]), "r"(b0), "r"(b1));
}
__device__ __forceinline__ void cpa(unsigned dst, const void* src) {
    asm volatile("cp.async.cg.shared.global [%0], [%1], 16;" :: "r"(dst), "l"(src));
}
#define CP_COMMIT() asm volatile("cp.async.commit_group;" ::: "memory")
#define CP_WAIT(n)  asm volatile("cp.async.wait_group %0;" :: "n"(n) : "memory")

// attn smem
#define SM_QHI 0u
#define SM_QLO 16384u
#define SM_KHI 32768u
#define SM_KLO 49152u
#define SM_VHI 65536u
#define SM_VLO 81920u
#define SMEM_ATTN (98304 + 2048)
// proj smem: 2 stages x 64KB (XHI,XLO,WHI,WLO each 16KB)
#define SMEM_PROJ (131072 + 1024)

// ---------------------------------------------------------------------------
// Pre-split fp32 -> bf16 hi/lo. blockIdx.y: 0..2 = X(q,k,v), 3..5 = W(q,k,v)
// ---------------------------------------------------------------------------
__global__ __launch_bounds__(256) void split_kernel(
    const float* __restrict__ q, const float* __restrict__ k, const float* __restrict__ v,
    const float* __restrict__ wq, const float* __restrict__ wk, const float* __restrict__ wv)
{
    const int z = blockIdx.y;
    const float* src = (z==0)?q:(z==1)?k:(z==2)?v:(z==3)?wq:(z==4)?wk:wv;
    __nv_bfloat16* dh; __nv_bfloat16* dl; size_t n4;
    if (z < 3) { dh = gXhi[z]; dl = gXlo[z]; n4 = NX/4; }
    else       { dh = gWhi[z-3]; dl = gWlo[z-3]; n4 = NW/4; }
    for (size_t i = blockIdx.x*256 + threadIdx.x; i < n4; i += (size_t)gridDim.x*256) {
        float4 x = *(const float4*)(src + i*4);
        float hx = tobf(x.x), hy = tobf(x.y), hz = tobf(x.z), hw = tobf(x.w);
        *(uint2*)(dh + i*4) = make_uint2(pk(hx,hy), pk(hz,hw));
        *(uint2*)(dl + i*4) = make_uint2(pk(x.x-hx, x.y-hy), pk(x.z-hz, x.w-hw));
    }
}

// ---------------------------------------------------------------------------
// Projections: y = X@W^T + b (compensated bf16 mma), Lorentz epilogue,
// outputs written as bf16 hi/lo. cp.async double-buffered K-chunks.
// ---------------------------------------------------------------------------
__global__ __launch_bounds__(256, 1) void proj_kernel(
    const float* __restrict__ bq, const float* __restrict__ sq,
    const float* __restrict__ bk, const float* __restrict__ sk,
    const float* __restrict__ bv, const float* __restrict__ sv)
{
    const int z = blockIdx.z;
    const float* bias = (z==0)?bq:(z==1)?bk:bv;
    const float* lsc  = (z==0)?sq:(z==1)?sk:sv;
    const __nv_bfloat16* Xhi = gXhi[z];
    const __nv_bfloat16* Xlo = gXlo[z];
    const __nv_bfloat16* Whi = gWhi[z];
    const __nv_bfloat16* Wlo = gWlo[z];

    extern __shared__ char smraw[];
    const unsigned sb = (smem_u32(smraw) + 1023u) & ~1023u;

    const int tid = threadIdx.x;
    const int w = tid >> 5, l = tid & 31;
    const int n0 = blockIdx.x * 128;
    const int m0 = blockIdx.y * 128;

    float cc[16][4];
#pragma unroll
    for (int i = 0; i < 16; i++)
#pragma unroll
        for (int j = 0; j < 4; j++) cc[i][j] = 0.f;

    const unsigned krow = (l & 7) + ((l & 16) >> 1);
    const unsigned kchalf = ((l >> 3) & 1) * 16;
    const unsigned qoff = (unsigned)(w * 16 + (l & 15)) * 128 + ((l >> 4) * 16);
    const int rr = tid >> 3, ch = tid & 7;           // staging row / chunk
    const unsigned swst = SWZ((unsigned)(rr * 128 + ch * 16));

    // issue stage s <- k-chunk kc
    auto issue = [&](int s, int kc) {
        unsigned base = sb + (unsigned)s * 65536u;
        const int k0 = kc * 64;
#pragma unroll
        for (int it = 0; it < 4; it++) {
            int r = rr + it * 32;
            unsigned sw = SWZ((unsigned)(r * 128 + ch * 16));
            cpa(base + sw,          Xhi + (size_t)(m0 + r) * Dz + k0 + ch * 8);
            cpa(base + 16384u + sw, Xlo + (size_t)(m0 + r) * Dz + k0 + ch * 8);
            cpa(base + 32768u + sw, Whi + (size_t)(n0 + r) * Dz + k0 + ch * 8);
            cpa(base + 49152u + sw, Wlo + (size_t)(n0 + r) * Dz + k0 + ch * 8);
        }
        CP_COMMIT();
    };
    (void)swst;

    issue(0, 0);
    for (int kc = 0; kc < 8; kc++) {
        __syncthreads();
        if (kc < 7) { issue((kc + 1) & 1, kc + 1); CP_WAIT(1); }
        else        { CP_WAIT(0); }
        __syncthreads();
        const unsigned base = sb + (unsigned)(kc & 1) * 65536u;

        unsigned ah[4][4], al[4][4];
#pragma unroll
        for (int c = 0; c < 4; c++) {
            unsigned sw = SWZ(qoff + c * 32);
            ldsm4(base + sw,          ah[c][0], ah[c][1], ah[c][2], ah[c][3]);
            ldsm4(base + 16384u + sw, al[c][0], al[c][1], al[c][2], al[c][3]);
        }
#pragma unroll
        for (int g = 0; g < 8; g++) {
            unsigned goff = (unsigned)(g * 16 + krow) * 128 + kchalf;
#pragma unroll
            for (int c = 0; c < 4; c++) {
                unsigned b0, b1, b2, b3, e0, e1, e2, e3;
                unsigned sw = SWZ(goff + c * 32);
                ldsm4(base + 32768u + sw, b0, b1, b2, b3);
                ldsm4(base + 49152u + sw, e0, e1, e2, e3);
                mma16816(cc[2*g],   ah[c], b0, b1);
                mma16816(cc[2*g+1], ah[c], b2, b3);
                mma16816(cc[2*g],   al[c], b0, b1);
                mma16816(cc[2*g+1], al[c], b2, b3);
                mma16816(cc[2*g],   ah[c], e0, e1);
                mma16816(cc[2*g+1], ah[c], e2, e3);
            }
        }
    }

    // ---- epilogue: bias + per-head Lorentz projection; write bf16 hi/lo ----
    const float es = expf(lsc[0]);
    const int colq = (l & 3) * 2;
    const int r0 = m0 + w * 16 + (l >> 2);
    const int hbase = n0 >> 6;

#pragma unroll
    for (int t = 0; t < 16; t++) {
        float bv0 = bias[n0 + t*8 + colq];
        float bv1 = bias[n0 + t*8 + colq + 1];
        cc[t][0] += bv0; cc[t][1] += bv1;
        cc[t][2] += bv0; cc[t][3] += bv1;
    }

    __nv_bfloat16* outh = gPhi[z];
    __nv_bfloat16* outl = gPlo[z];

#pragma unroll
    for (int g2 = 0; g2 < 2; g2++) {
        float pp0 = 0.f, pp1 = 0.f;
#pragma unroll
        for (int tt = 0; tt < 8; tt++) {
            int t = g2 * 8 + tt;
            bool istime = (colq == 0) && (tt == 0);
            float y00 = cc[t][0], y01 = cc[t][1], y10 = cc[t][2], y11 = cc[t][3];
            pp0 += (istime ? 0.f : y00*y00) + y01*y01;
            pp1 += (istime ? 0.f : y10*y10) + y11*y11;
        }
        pp0 += __shfl_xor_sync(0xffffffffu, pp0, 1);
        pp0 += __shfl_xor_sync(0xffffffffu, pp0, 2);
        pp1 += __shfl_xor_sync(0xffffffffu, pp1, 1);
        pp1 += __shfl_xor_sync(0xffffffffu, pp1, 2);
        float t0 = 0.f, t1 = 0.f, f0 = 0.f, f1 = 0.f;
        if ((l & 3) == 0) {
            t0 = es / (1.f + expf(-cc[g2*8][0])) + 1.1f;
            t1 = es / (1.f + expf(-cc[g2*8][2])) + 1.1f;
            f0 = sqrtf((t0*t0 - 1.f) / fmaxf(pp0, 1e-8f));
            f1 = sqrtf((t1*t1 - 1.f) / fmaxf(pp1, 1e-8f));
        }
        int src = l & ~3;
        t0 = __shfl_sync(0xffffffffu, t0, src);
        t1 = __shfl_sync(0xffffffffu, t1, src);
        f0 = __shfl_sync(0xffffffffu, f0, src);
        f1 = __shfl_sync(0xffffffffu, f1, src);

        int h = hbase + g2;
        int bb0 = r0 >> 11, s0 = r0 & (Sz - 1);
        int r1 = r0 + 8;
        int bb1 = r1 >> 11, s1 = r1 & (Sz - 1);
        size_t o0 = ((size_t)((bb0*Hz + h)*Sz + s0)) * DPH;
        size_t o1 = ((size_t)((bb1*Hz + h)*Sz + s1)) * DPH;
#pragma unroll
        for (int tt = 0; tt < 8; tt++) {
            int t = g2 * 8 + tt;
            int lc = tt * 8 + colq;
            bool istime = (lc == 0);
            float v00 = istime ? ((z == 0) ? -t0 : t0) : cc[t][0] * f0;
            float v01 = cc[t][1] * f0;
            float v10 = istime ? ((z == 0) ? -t1 : t1) : cc[t][2] * f1;
            float v11 = cc[t][3] * f1;
            float h00 = tobf(v00), h01 = tobf(v01), h10 = tobf(v10), h11 = tobf(v11);
            *(unsigned*)(outh + o0 + lc) = pk(h00, h01);
            *(unsigned*)(outl + o0 + lc) = pk(v00 - h00, v01 - h01);
            *(unsigned*)(outh + o1 + lc) = pk(h10, h11);
            *(unsigned*)(outl + o1 + lc) = pk(v10 - h10, v11 - h11);
        }
    }
}

// ---------------------------------------------------------------------------
// Fused causal attention (mma.sync bf16, 3-term compensated), cp.async staging.
// ---------------------------------------------------------------------------
__global__ __launch_bounds__(256, 1) void attn_kernel(
    float* __restrict__ attn, float* __restrict__ ctx,
    const float* __restrict__ scale_ptr)
{
    extern __shared__ char smraw[];
    const unsigned sb = (smem_u32(smraw) + 1023u) & ~1023u;

    const int blk = blockIdx.x;
    const int bh = blk & 15;
    const int qt = (NQT - 1) - (blk >> 4);
    const int q0 = qt * QT;
    const int b = bh >> 3, h = bh & 7;

    const int tid = threadIdx.x;
    const int w = tid >> 5, l = tid & 31;

    const float inv_as = 1.f / scale_ptr[0];
    const __nv_bfloat16* Qhi = gPhi[0] + (size_t)bh * Sz * DPH;
    const __nv_bfloat16* Qlo = gPlo[0] + (size_t)bh * Sz * DPH;
    const __nv_bfloat16* Khi = gPhi[1] + (size_t)bh * Sz * DPH;
    const __nv_bfloat16* Klo = gPlo[1] + (size_t)bh * Sz * DPH;
    const __nv_bfloat16* Vhi = gPhi[2] + (size_t)bh * Sz * DPH;
    const __nv_bfloat16* Vlo = gPlo[2] + (size_t)bh * Sz * DPH;
    float* arow = attn + (size_t)bh * Sz * Sz;

    const int rr = tid >> 3, chk = tid & 7;

    // Q tile via cp.async
#pragma unroll
    for (int it = 0; it < 4; it++) {
        int r = rr + it * 32;
        unsigned sw = SWZ((unsigned)(r * 128 + chk * 16));
        cpa(sb + SM_QHI + sw, Qhi + (size_t)(q0 + r) * DPH + chk * 8);
        cpa(sb + SM_QLO + sw, Qlo + (size_t)(q0 + r) * DPH + chk * 8);
    }
    CP_COMMIT(); CP_WAIT(0);
    __syncthreads();

    unsigned qh[4][4], ql[4][4];
    {
        unsigned qoff = (unsigned)(w * 16 + (l & 15)) * 128 + ((l >> 4) * 16);
#pragma unroll
        for (int c = 0; c < 4; c++) {
            unsigned sw = SWZ(qoff + c * 32);
            ldsm4(sb + SM_QHI + sw, qh[c][0], qh[c][1], qh[c][2], qh[c][3]);
            ldsm4(sb + SM_QLO + sw, ql[c][0], ql[c][1], ql[c][2], ql[c][3]);
        }
    }

    const unsigned krow = (l & 7) + ((l & 16) >> 1);
    const unsigned kchalf = ((l >> 3) & 1) * 16;
    const unsigned vt = l >> 3;
    const unsigned vrow = (l & 7) + ((vt & 1) << 3);
    const unsigned vd8 = (vt >> 1) * 16;

    float cc[8][4];
#pragma unroll
    for (int i = 0; i < 8; i++)
#pragma unroll
        for (int j = 0; j < 4; j++) cc[i][j] = 0.f;
    float lsum0 = 0.f, lsum1 = 0.f;

    const int row0 = w * 16 + (l >> 2);
    const int gq0 = q0 + row0, gq1 = gq0 + 8;
    const int colq = (l & 3) * 2;

    for (int kt = 0; kt <= qt; ++kt) {
        const int k0 = kt * QT;
        __syncthreads();
#pragma unroll
        for (int it = 0; it < 4; it++) {
            int r = rr + it * 32;
            unsigned sw = SWZ((unsigned)(r * 128 + chk * 16));
            const size_t go = (size_t)(k0 + r) * DPH + chk * 8;
            cpa(sb + SM_KHI + sw, Khi + go);
            cpa(sb + SM_KLO + sw, Klo + go);
            cpa(sb + SM_VHI + sw, Vhi + go);
            cpa(sb + SM_VLO + sw, Vlo + go);
        }
        CP_COMMIT(); CP_WAIT(0);
        __syncthreads();

        float sc[16][4];
#pragma unroll
        for (int i = 0; i < 16; i++)
#pragma unroll
            for (int j = 0; j < 4; j++) sc[i][j] = 0.f;
#pragma unroll
        for (int g = 0; g < 8; g++) {
            unsigned goff = (unsigned)(g * 16 + krow) * 128 + kchalf;
#pragma unroll
            for (int c = 0; c < 4; c++) {
                unsigned b0, b1, b2, b3, e0, e1, e2, e3;
                unsigned sw = SWZ(goff + c * 32);
                ldsm4(sb + SM_KHI + sw, b0, b1, b2, b3);
                ldsm4(sb + SM_KLO + sw, e0, e1, e2, e3);
                mma16816(sc[2*g],   qh[c], b0, b1);
                mma16816(sc[2*g+1], qh[c], b2, b3);
                mma16816(sc[2*g],   ql[c], b0, b1);
                mma16816(sc[2*g+1], ql[c], b2, b3);
                mma16816(sc[2*g],   qh[c], e0, e1);
                mma16816(sc[2*g+1], qh[c], e2, e3);
            }
        }

        const bool diag = (kt == qt);
        float* p0 = arow + (size_t)gq0 * Sz + k0 + colq;
        float* p1 = arow + (size_t)gq1 * Sz + k0 + colq;
#pragma unroll
        for (int t = 0; t < 16; t++) {
            int gk = k0 + t * 8 + colq;
            float v0 = __expf((2.f * sc[t][0] + 2.f) * inv_as);
            float v1 = __expf((2.f * sc[t][1] + 2.f) * inv_as);
            float v2 = __expf((2.f * sc[t][2] + 2.f) * inv_as);
            float v3 = __expf((2.f * sc[t][3] + 2.f) * inv_as);
            if (diag) {
                if (gk > gq0)     v0 = 0.f;
                if (gk + 1 > gq0) v1 = 0.f;
                if (gk > gq1)     v2 = 0.f;
                if (gk + 1 > gq1) v3 = 0.f;
            }
            sc[t][0] = v0; sc[t][1] = v1; sc[t][2] = v2; sc[t][3] = v3;
            lsum0 += v0 + v1;
            lsum1 += v2 + v3;
            *(float2*)(p0 + t*8) = make_float2(v0, v1);
            *(float2*)(p1 + t*8) = make_float2(v2, v3);
        }

#pragma unroll
        for (int kc = 0; kc < 8; kc++) {
            unsigned ah[4], al[4];
            {
                float x0 = sc[2*kc][0], x1 = sc[2*kc][1], x2 = sc[2*kc][2], x3 = sc[2*kc][3];
                float y0 = sc[2*kc+1][0], y1 = sc[2*kc+1][1], y2 = sc[2*kc+1][2], y3 = sc[2*kc+1][3];
                float hx0 = tobf(x0), hx1 = tobf(x1), hx2 = tobf(x2), hx3 = tobf(x3);
                float hy0 = tobf(y0), hy1 = tobf(y1), hy2 = tobf(y2), hy3 = tobf(y3);
                ah[0] = pk(hx0, hx1); ah[1] = pk(hx2, hx3);
                ah[2] = pk(hy0, hy1); ah[3] = pk(hy2, hy3);
                al[0] = pk(x0 - hx0, x1 - hx1); al[1] = pk(x2 - hx2, x3 - hx3);
                al[2] = pk(y0 - hy0, y1 - hy1); al[3] = pk(y2 - hy2, y3 - hy3);
            }
            unsigned koff = (unsigned)(kc * 16 + vrow) * 128 + vd8;
#pragma unroll
            for (int g = 0; g < 4; g++) {
                unsigned b0, b1, b2, b3, e0, e1, e2, e3;
                unsigned sw = SWZ(koff + g * 32);
                ldsm4t(sb + SM_VHI + sw, b0, b1, b2, b3);
                ldsm4t(sb + SM_VLO + sw, e0, e1, e2, e3);
                mma16816(cc[2*g],   ah, b0, b1);
                mma16816(cc[2*g+1], ah, b2, b3);
                mma16816(cc[2*g],   al, b0, b1);
                mma16816(cc[2*g+1], al, b2, b3);
                mma16816(cc[2*g],   ah, e0, e1);
                mma16816(cc[2*g+1], ah, e2, e3);
            }
        }
    }

    lsum0 += __shfl_xor_sync(0xffffffffu, lsum0, 1);
    lsum0 += __shfl_xor_sync(0xffffffffu, lsum0, 2);
    lsum1 += __shfl_xor_sync(0xffffffffu, lsum1, 1);
    lsum1 += __shfl_xor_sync(0xffffffffu, lsum1, 2);
    if ((l & 3) == 0) {
        g_l[bh*Sz + gq0] = lsum0;
        g_l[bh*Sz + gq1] = lsum1;
    }

    float pp0 = 0.f, pp1 = 0.f;
#pragma unroll
    for (int t = 0; t < 8; t++) {
        float a0 = cc[t][0], a1 = cc[t][1], a2 = cc[t][2], a3 = cc[t][3];
        float s0 = (t == 0 && (l & 3) == 0) ? -a0*a0 : a0*a0;
        float s2 = (t == 0 && (l & 3) == 0) ? -a2*a2 : a2*a2;
        pp0 += s0 + a1*a1;
        pp1 += s2 + a3*a3;
    }
    pp0 += __shfl_xor_sync(0xffffffffu, pp0, 1);
    pp0 += __shfl_xor_sync(0xffffffffu, pp0, 2);
    pp1 += __shfl_xor_sync(0xffffffffu, pp1, 1);
    pp1 += __shfl_xor_sync(0xffffffffu, pp1, 2);
    float inv0 = rsqrtf(fmaxf(fabsf(pp0), 1e-8f));
    float inv1 = rsqrtf(fmaxf(fabsf(pp1), 1e-8f));
    float* c0p = ctx + ((size_t)((b*Sz + gq0)*Hz + h)) * DPH + colq;
    float* c1p = ctx + ((size_t)((b*Sz + gq1)*Hz + h)) * DPH + colq;
#pragma unroll
    for (int t = 0; t < 8; t++) {
        *(float2*)(c0p + t*8) = make_float2(cc[t][0]*inv0, cc[t][1]*inv0);
        *(float2*)(c1p + t*8) = make_float2(cc[t][2]*inv1, cc[t][3]*inv1);
    }
}

// ---------------------------------------------------------------------------
__global__ __launch_bounds__(256) void norm_kernel(float* __restrict__ attn)
{
    const int q = blockIdx.x;
    const int bh = blockIdx.y;
    const float inv = 1.f / g_l[bh*Sz + q];
    float4* row = (float4*)(attn + (size_t)bh * Sz * Sz + (size_t)q * Sz);
    const float4 zero = make_float4(0.f, 0.f, 0.f, 0.f);
#pragma unroll
    for (int it = 0; it < 2; it++) {
        int p = threadIdx.x + it * 256;
        if (p * 4 > q) {
            row[p] = zero;
        } else {
            float4 v = row[p];
            v.x *= inv; v.y *= inv; v.z *= inv; v.w *= inv;
            row[p] = v;
        }
    }
}

extern "C" void kernel_launch(void* const* d_in, const int* in_sizes, int n_in,
                              void* d_out, int out_size)
{
    const float* key   = (const float*)d_in[0];
    const float* value = (const float*)d_in[1];
    const float* query = (const float*)d_in[2];
    const float* Wq = (const float*)d_in[4];
    const float* bq = (const float*)d_in[5];
    const float* sq = (const float*)d_in[6];
    const float* Wk = (const float*)d_in[7];
    const float* bk = (const float*)d_in[8];
    const float* sk = (const float*)d_in[9];
    const float* Wv = (const float*)d_in[10];
    const float* bv = (const float*)d_in[11];
    const float* sv = (const float*)d_in[12];
    const float* att_scale = (const float*)d_in[13];

    float* ctx  = (float*)d_out;
    float* attn = ctx + (size_t)Bz * Sz * Dz;

    dim3 gs(512, 6);
    split_kernel<<<gs, 256>>>(query, key, value, Wq, Wk, Wv);

    cudaFuncSetAttribute(proj_kernel, cudaFuncAttributeMaxDynamicSharedMemorySize, SMEM_PROJ);
    dim3 gp(Dz / 128, Mrows / 128, 3);
    proj_kernel<<<gp, 256, SMEM_PROJ>>>(bq, sq, bk, sk, bv, sv);

    cudaFuncSetAttribute(attn_kernel, cudaFuncAttributeMaxDynamicSharedMemorySize, SMEM_ATTN);
    attn_kernel<<<BHn * NQT, 256, SMEM_ATTN>>>(attn, ctx, att_scale);

    dim3 gn(Sz, BHn);
    norm_kernel<<<gn, 256>>>(attn);
}

// round 9
// speedup vs baseline: 4.0649x; 1.0645x over previous
#include <cuda_runtime.h>
#include <cuda_bf16.h>
#include <math.h>

#define Bz 2
#define Sz 2048
#define Dz 512
#define Hz 8
#define DPH 64
#define BHn (Bz*Hz)
#define Mrows (Bz*Sz)
#define QT 128
#define NQT (Sz/QT)
#define NX ((size_t)Mrows*Dz)
#define NW ((size_t)Dz*Dz)

__device__ __nv_bfloat16 gXhi[3][NX];
__device__ __nv_bfloat16 gXlo[3][NX];
__device__ __nv_bfloat16 gWhi[3][NW];
__device__ __nv_bfloat16 gWlo[3][NW];
__device__ __nv_bfloat16 gPhi[3][(size_t)BHn*Sz*DPH];
__device__ __nv_bfloat16 gPlo[3][(size_t)BHn*Sz*DPH];
__device__ float g_l[BHn*Sz];

// ===================== helpers =====================
__device__ __forceinline__ unsigned smem_u32(const void* p) {
    unsigned a;
    asm("{ .reg .u64 t; cvta.to.shared.u64 t, %1; cvt.u32.u64 %0, t; }" : "=r"(a) : "l"(p));
    return a;
}
#define SWZ(x) ((x) ^ (((x) >> 3) & 0x70))
__device__ __forceinline__ float tobf(float x) { return __bfloat162float(__float2bfloat16_rn(x)); }
__device__ __forceinline__ unsigned pk(float a, float b) {
    __nv_bfloat162 t = __floats2bfloat162_rn(a, b);
    return *(unsigned*)&t;
}
__device__ __forceinline__ void ldsm4(unsigned addr, unsigned& r0, unsigned& r1, unsigned& r2, unsigned& r3) {
    asm volatile("ldmatrix.sync.aligned.m8n8.x4.shared.b16 {%0,%1,%2,%3}, [%4];"
        : "=r"(r0), "=r"(r1), "=r"(r2), "=r"(r3) : "r"(addr));
}
__device__ __forceinline__ void ldsm4t(unsigned addr, unsigned& r0, unsigned& r1, unsigned& r2, unsigned& r3) {
    asm volatile("ldmatrix.sync.aligned.m8n8.x4.trans.shared.b16 {%0,%1,%2,%3}, [%4];"
        : "=r"(r0), "=r"(r1), "=r"(r2), "=r"(r3) : "r"(addr));
}
__device__ __forceinline__ void mma16816(float* c, const unsigned* a, unsigned b0, unsigned b1) {
    asm volatile("mma.sync.aligned.m16n8k16.row.col.f32.bf16.bf16.f32 "
        "{%0,%1,%2,%3},{%4,%5,%6,%7},{%8,%9},{%0,%1,%2,%3};"
        : "+f"(c[0]), "+f"(c[1]), "+f"(c[2]), "+f"(c[3])
        : "r"(a[0]), "r"(a[1]), "r"(a[2]), "r"(a[3]), "r"(b0), "r"(b1));
}
__device__ __forceinline__ void cpa(unsigned dst, const void* src) {
    asm volatile("cp.async.cg.shared.global [%0], [%1], 16;" :: "r"(dst), "l"(src));
}
#define CP_COMMIT() asm volatile("cp.async.commit_group;" ::: "memory")
#define CP_WAIT(n)  asm volatile("cp.async.wait_group %0;" :: "n"(n) : "memory")

// attn smem: Q 32KB + 2 stages x 64KB (KHI,KLO,VHI,VLO)
#define SM_QHI 0u
#define SM_QLO 16384u
#define SM_KV  32768u
#define SMEM_ATTN (32768 + 2*65536 + 1024)
// pass2 smem: Q 32KB + 2 stages x 32KB (KHI,KLO)
#define SMEM_P2 (32768 + 2*32768 + 1024)
// proj smem: 2 stages x 64KB
#define SMEM_PROJ (131072 + 1024)

// ---------------------------------------------------------------------------
__global__ __launch_bounds__(256) void split_kernel(
    const float* __restrict__ q, const float* __restrict__ k, const float* __restrict__ v,
    const float* __restrict__ wq, const float* __restrict__ wk, const float* __restrict__ wv)
{
    const int z = blockIdx.y;
    const float* src = (z==0)?q:(z==1)?k:(z==2)?v:(z==3)?wq:(z==4)?wk:wv;
    __nv_bfloat16* dh; __nv_bfloat16* dl; size_t n4;
    if (z < 3) { dh = gXhi[z]; dl = gXlo[z]; n4 = NX/4; }
    else       { dh = gWhi[z-3]; dl = gWlo[z-3]; n4 = NW/4; }
    for (size_t i = blockIdx.x*256 + threadIdx.x; i < n4; i += (size_t)gridDim.x*256) {
        float4 x = *(const float4*)(src + i*4);
        float hx = tobf(x.x), hy = tobf(x.y), hz = tobf(x.z), hw = tobf(x.w);
        *(uint2*)(dh + i*4) = make_uint2(pk(hx,hy), pk(hz,hw));
        *(uint2*)(dl + i*4) = make_uint2(pk(x.x-hx, x.y-hy), pk(x.z-hz, x.w-hw));
    }
}

// ---------------------------------------------------------------------------
// Projections: y = X@W^T + b (compensated bf16 mma), Lorentz epilogue,
// outputs bf16 hi/lo. cp.async double-buffered K-chunks.
// ---------------------------------------------------------------------------
__global__ __launch_bounds__(256, 1) void proj_kernel(
    const float* __restrict__ bq, const float* __restrict__ sq,
    const float* __restrict__ bk, const float* __restrict__ sk,
    const float* __restrict__ bv, const float* __restrict__ sv)
{
    const int z = blockIdx.z;
    const float* bias = (z==0)?bq:(z==1)?bk:bv;
    const float* lsc  = (z==0)?sq:(z==1)?sk:sv;
    const __nv_bfloat16* Xhi = gXhi[z];
    const __nv_bfloat16* Xlo = gXlo[z];
    const __nv_bfloat16* Whi = gWhi[z];
    const __nv_bfloat16* Wlo = gWlo[z];

    extern __shared__ char smraw[];
    const unsigned sb = (smem_u32(smraw) + 1023u) & ~1023u;

    const int tid = threadIdx.x;
    const int w = tid >> 5, l = tid & 31;
    const int n0 = blockIdx.x * 128;
    const int m0 = blockIdx.y * 128;

    float cc[16][4];
#pragma unroll
    for (int i = 0; i < 16; i++)
#pragma unroll
        for (int j = 0; j < 4; j++) cc[i][j] = 0.f;

    const unsigned krow = (l & 7) + ((l & 16) >> 1);
    const unsigned kchalf = ((l >> 3) & 1) * 16;
    const unsigned qoff = (unsigned)(w * 16 + (l & 15)) * 128 + ((l >> 4) * 16);
    const int rr = tid >> 3, ch = tid & 7;

    auto issue = [&](int s, int kc) {
        unsigned base = sb + (unsigned)s * 65536u;
        const int k0 = kc * 64;
#pragma unroll
        for (int it = 0; it < 4; it++) {
            int r = rr + it * 32;
            unsigned sw = SWZ((unsigned)(r * 128 + ch * 16));
            cpa(base + sw,          Xhi + (size_t)(m0 + r) * Dz + k0 + ch * 8);
            cpa(base + 16384u + sw, Xlo + (size_t)(m0 + r) * Dz + k0 + ch * 8);
            cpa(base + 32768u + sw, Whi + (size_t)(n0 + r) * Dz + k0 + ch * 8);
            cpa(base + 49152u + sw, Wlo + (size_t)(n0 + r) * Dz + k0 + ch * 8);
        }
        CP_COMMIT();
    };

    issue(0, 0);
    for (int kc = 0; kc < 8; kc++) {
        __syncthreads();
        if (kc < 7) { issue((kc + 1) & 1, kc + 1); CP_WAIT(1); }
        else        { CP_WAIT(0); }
        __syncthreads();
        const unsigned base = sb + (unsigned)(kc & 1) * 65536u;

        unsigned ah[4][4], al[4][4];
#pragma unroll
        for (int c = 0; c < 4; c++) {
            unsigned sw = SWZ(qoff + c * 32);
            ldsm4(base + sw,          ah[c][0], ah[c][1], ah[c][2], ah[c][3]);
            ldsm4(base + 16384u + sw, al[c][0], al[c][1], al[c][2], al[c][3]);
        }
#pragma unroll
        for (int g = 0; g < 8; g++) {
            unsigned goff = (unsigned)(g * 16 + krow) * 128 + kchalf;
#pragma unroll
            for (int c = 0; c < 4; c++) {
                unsigned b0, b1, b2, b3, e0, e1, e2, e3;
                unsigned sw = SWZ(goff + c * 32);
                ldsm4(base + 32768u + sw, b0, b1, b2, b3);
                ldsm4(base + 49152u + sw, e0, e1, e2, e3);
                mma16816(cc[2*g],   ah[c], b0, b1);
                mma16816(cc[2*g+1], ah[c], b2, b3);
                mma16816(cc[2*g],   al[c], b0, b1);
                mma16816(cc[2*g+1], al[c], b2, b3);
                mma16816(cc[2*g],   ah[c], e0, e1);
                mma16816(cc[2*g+1], ah[c], e2, e3);
            }
        }
    }

    const float es = expf(lsc[0]);
    const int colq = (l & 3) * 2;
    const int r0 = m0 + w * 16 + (l >> 2);
    const int hbase = n0 >> 6;

#pragma unroll
    for (int t = 0; t < 16; t++) {
        float bv0 = bias[n0 + t*8 + colq];
        float bv1 = bias[n0 + t*8 + colq + 1];
        cc[t][0] += bv0; cc[t][1] += bv1;
        cc[t][2] += bv0; cc[t][3] += bv1;
    }

    __nv_bfloat16* outh = gPhi[z];
    __nv_bfloat16* outl = gPlo[z];

#pragma unroll
    for (int g2 = 0; g2 < 2; g2++) {
        float pp0 = 0.f, pp1 = 0.f;
#pragma unroll
        for (int tt = 0; tt < 8; tt++) {
            int t = g2 * 8 + tt;
            bool istime = (colq == 0) && (tt == 0);
            float y00 = cc[t][0], y01 = cc[t][1], y10 = cc[t][2], y11 = cc[t][3];
            pp0 += (istime ? 0.f : y00*y00) + y01*y01;
            pp1 += (istime ? 0.f : y10*y10) + y11*y11;
        }
        pp0 += __shfl_xor_sync(0xffffffffu, pp0, 1);
        pp0 += __shfl_xor_sync(0xffffffffu, pp0, 2);
        pp1 += __shfl_xor_sync(0xffffffffu, pp1, 1);
        pp1 += __shfl_xor_sync(0xffffffffu, pp1, 2);
        float t0 = 0.f, t1 = 0.f, f0 = 0.f, f1 = 0.f;
        if ((l & 3) == 0) {
            t0 = es / (1.f + expf(-cc[g2*8][0])) + 1.1f;
            t1 = es / (1.f + expf(-cc[g2*8][2])) + 1.1f;
            f0 = sqrtf((t0*t0 - 1.f) / fmaxf(pp0, 1e-8f));
            f1 = sqrtf((t1*t1 - 1.f) / fmaxf(pp1, 1e-8f));
        }
        int src = l & ~3;
        t0 = __shfl_sync(0xffffffffu, t0, src);
        t1 = __shfl_sync(0xffffffffu, t1, src);
        f0 = __shfl_sync(0xffffffffu, f0, src);
        f1 = __shfl_sync(0xffffffffu, f1, src);

        int h = hbase + g2;
        int bb0 = r0 >> 11, s0 = r0 & (Sz - 1);
        int r1 = r0 + 8;
        int bb1 = r1 >> 11, s1 = r1 & (Sz - 1);
        size_t o0 = ((size_t)((bb0*Hz + h)*Sz + s0)) * DPH;
        size_t o1 = ((size_t)((bb1*Hz + h)*Sz + s1)) * DPH;
#pragma unroll
        for (int tt = 0; tt < 8; tt++) {
            int t = g2 * 8 + tt;
            int lc = tt * 8 + colq;
            bool istime = (lc == 0);
            float v00 = istime ? ((z == 0) ? -t0 : t0) : cc[t][0] * f0;
            float v01 = cc[t][1] * f0;
            float v10 = istime ? ((z == 0) ? -t1 : t1) : cc[t][2] * f1;
            float v11 = cc[t][3] * f1;
            float h00 = tobf(v00), h01 = tobf(v01), h10 = tobf(v10), h11 = tobf(v11);
            *(unsigned*)(outh + o0 + lc) = pk(h00, h01);
            *(unsigned*)(outl + o0 + lc) = pk(v00 - h00, v01 - h01);
            *(unsigned*)(outh + o1 + lc) = pk(h10, h11);
            *(unsigned*)(outl + o1 + lc) = pk(v10 - h10, v11 - h11);
        }
    }
}

// ---------------------------------------------------------------------------
// Attention pass 1: l row-sums + ctx. No P writes. Double-buffered cp.async.
// ---------------------------------------------------------------------------
__global__ __launch_bounds__(256, 1) void attn_kernel(
    float* __restrict__ ctx, const float* __restrict__ scale_ptr)
{
    extern __shared__ char smraw[];
    const unsigned sb = (smem_u32(smraw) + 1023u) & ~1023u;

    const int blk = blockIdx.x;
    const int bh = blk & 15;
    const int qt = (NQT - 1) - (blk >> 4);
    const int q0 = qt * QT;
    const int b = bh >> 3, h = bh & 7;

    const int tid = threadIdx.x;
    const int w = tid >> 5, l = tid & 31;

    const float inv_as = 1.f / scale_ptr[0];
    const __nv_bfloat16* Qhi = gPhi[0] + (size_t)bh * Sz * DPH;
    const __nv_bfloat16* Qlo = gPlo[0] + (size_t)bh * Sz * DPH;
    const __nv_bfloat16* Khi = gPhi[1] + (size_t)bh * Sz * DPH;
    const __nv_bfloat16* Klo = gPlo[1] + (size_t)bh * Sz * DPH;
    const __nv_bfloat16* Vhi = gPhi[2] + (size_t)bh * Sz * DPH;
    const __nv_bfloat16* Vlo = gPlo[2] + (size_t)bh * Sz * DPH;

    const int rr = tid >> 3, chk = tid & 7;

    auto issue_kv = [&](int s, int kt) {
        unsigned base = sb + SM_KV + (unsigned)s * 65536u;
        const int k0 = kt * QT;
#pragma unroll
        for (int it = 0; it < 4; it++) {
            int r = rr + it * 32;
            unsigned sw = SWZ((unsigned)(r * 128 + chk * 16));
            const size_t go = (size_t)(k0 + r) * DPH + chk * 8;
            cpa(base + sw,          Khi + go);
            cpa(base + 16384u + sw, Klo + go);
            cpa(base + 32768u + sw, Vhi + go);
            cpa(base + 49152u + sw, Vlo + go);
        }
        CP_COMMIT();
    };

    // Q tile + first KV stage
#pragma unroll
    for (int it = 0; it < 4; it++) {
        int r = rr + it * 32;
        unsigned sw = SWZ((unsigned)(r * 128 + chk * 16));
        cpa(sb + SM_QHI + sw, Qhi + (size_t)(q0 + r) * DPH + chk * 8);
        cpa(sb + SM_QLO + sw, Qlo + (size_t)(q0 + r) * DPH + chk * 8);
    }
    CP_COMMIT();
    issue_kv(0, 0);
    CP_WAIT(0);
    __syncthreads();

    unsigned qh[4][4], ql[4][4];
    {
        unsigned qoff = (unsigned)(w * 16 + (l & 15)) * 128 + ((l >> 4) * 16);
#pragma unroll
        for (int c = 0; c < 4; c++) {
            unsigned sw = SWZ(qoff + c * 32);
            ldsm4(sb + SM_QHI + sw, qh[c][0], qh[c][1], qh[c][2], qh[c][3]);
            ldsm4(sb + SM_QLO + sw, ql[c][0], ql[c][1], ql[c][2], ql[c][3]);
        }
    }

    const unsigned krow = (l & 7) + ((l & 16) >> 1);
    const unsigned kchalf = ((l >> 3) & 1) * 16;
    const unsigned vt = l >> 3;
    const unsigned vrow = (l & 7) + ((vt & 1) << 3);
    const unsigned vd8 = (vt >> 1) * 16;

    float cc[8][4];
#pragma unroll
    for (int i = 0; i < 8; i++)
#pragma unroll
        for (int j = 0; j < 4; j++) cc[i][j] = 0.f;
    float lsum0 = 0.f, lsum1 = 0.f;

    const int row0 = w * 16 + (l >> 2);
    const int gq0 = q0 + row0, gq1 = gq0 + 8;
    const int colq = (l & 3) * 2;

    for (int kt = 0; kt <= qt; ++kt) {
        const int k0 = kt * QT;
        if (kt < qt) { issue_kv((kt + 1) & 1, kt + 1); CP_WAIT(1); }
        __syncthreads();
        const unsigned kb = sb + SM_KV + (unsigned)(kt & 1) * 65536u;

        float sc[16][4];
#pragma unroll
        for (int i = 0; i < 16; i++)
#pragma unroll
            for (int j = 0; j < 4; j++) sc[i][j] = 0.f;
#pragma unroll
        for (int g = 0; g < 8; g++) {
            unsigned goff = (unsigned)(g * 16 + krow) * 128 + kchalf;
#pragma unroll
            for (int c = 0; c < 4; c++) {
                unsigned b0, b1, b2, b3, e0, e1, e2, e3;
                unsigned sw = SWZ(goff + c * 32);
                ldsm4(kb + sw,          b0, b1, b2, b3);
                ldsm4(kb + 16384u + sw, e0, e1, e2, e3);
                mma16816(sc[2*g],   qh[c], b0, b1);
                mma16816(sc[2*g+1], qh[c], b2, b3);
                mma16816(sc[2*g],   ql[c], b0, b1);
                mma16816(sc[2*g+1], ql[c], b2, b3);
                mma16816(sc[2*g],   qh[c], e0, e1);
                mma16816(sc[2*g+1], qh[c], e2, e3);
            }
        }

        const bool diag = (kt == qt);
#pragma unroll
        for (int t = 0; t < 16; t++) {
            int gk = k0 + t * 8 + colq;
            float v0 = __expf((2.f * sc[t][0] + 2.f) * inv_as);
            float v1 = __expf((2.f * sc[t][1] + 2.f) * inv_as);
            float v2 = __expf((2.f * sc[t][2] + 2.f) * inv_as);
            float v3 = __expf((2.f * sc[t][3] + 2.f) * inv_as);
            if (diag) {
                if (gk > gq0)     v0 = 0.f;
                if (gk + 1 > gq0) v1 = 0.f;
                if (gk > gq1)     v2 = 0.f;
                if (gk + 1 > gq1) v3 = 0.f;
            }
            sc[t][0] = v0; sc[t][1] = v1; sc[t][2] = v2; sc[t][3] = v3;
            lsum0 += v0 + v1;
            lsum1 += v2 + v3;
        }

#pragma unroll
        for (int kc = 0; kc < 8; kc++) {
            unsigned ah[4], al[4];
            {
                float x0 = sc[2*kc][0], x1 = sc[2*kc][1], x2 = sc[2*kc][2], x3 = sc[2*kc][3];
                float y0 = sc[2*kc+1][0], y1 = sc[2*kc+1][1], y2 = sc[2*kc+1][2], y3 = sc[2*kc+1][3];
                float hx0 = tobf(x0), hx1 = tobf(x1), hx2 = tobf(x2), hx3 = tobf(x3);
                float hy0 = tobf(y0), hy1 = tobf(y1), hy2 = tobf(y2), hy3 = tobf(y3);
                ah[0] = pk(hx0, hx1); ah[1] = pk(hx2, hx3);
                ah[2] = pk(hy0, hy1); ah[3] = pk(hy2, hy3);
                al[0] = pk(x0 - hx0, x1 - hx1); al[1] = pk(x2 - hx2, x3 - hx3);
                al[2] = pk(y0 - hy0, y1 - hy1); al[3] = pk(y2 - hy2, y3 - hy3);
            }
            unsigned koff = (unsigned)(kc * 16 + vrow) * 128 + vd8;
#pragma unroll
            for (int g = 0; g < 4; g++) {
                unsigned b0, b1, b2, b3, e0, e1, e2, e3;
                unsigned sw = SWZ(koff + g * 32);
                ldsm4t(kb + 32768u + sw, b0, b1, b2, b3);
                ldsm4t(kb + 49152u + sw, e0, e1, e2, e3);
                mma16816(cc[2*g],   ah, b0, b1);
                mma16816(cc[2*g+1], ah, b2, b3);
                mma16816(cc[2*g],   al, b0, b1);
                mma16816(cc[2*g+1], al, b2, b3);
                mma16816(cc[2*g],   ah, e0, e1);
                mma16816(cc[2*g+1], ah, e2, e3);
            }
        }
        __syncthreads();
    }

    lsum0 += __shfl_xor_sync(0xffffffffu, lsum0, 1);
    lsum0 += __shfl_xor_sync(0xffffffffu, lsum0, 2);
    lsum1 += __shfl_xor_sync(0xffffffffu, lsum1, 1);
    lsum1 += __shfl_xor_sync(0xffffffffu, lsum1, 2);
    if ((l & 3) == 0) {
        g_l[bh*Sz + gq0] = lsum0;
        g_l[bh*Sz + gq1] = lsum1;
    }

    float pp0 = 0.f, pp1 = 0.f;
#pragma unroll
    for (int t = 0; t < 8; t++) {
        float a0 = cc[t][0], a1 = cc[t][1], a2 = cc[t][2], a3 = cc[t][3];
        float s0 = (t == 0 && (l & 3) == 0) ? -a0*a0 : a0*a0;
        float s2 = (t == 0 && (l & 3) == 0) ? -a2*a2 : a2*a2;
        pp0 += s0 + a1*a1;
        pp1 += s2 + a3*a3;
    }
    pp0 += __shfl_xor_sync(0xffffffffu, pp0, 1);
    pp0 += __shfl_xor_sync(0xffffffffu, pp0, 2);
    pp1 += __shfl_xor_sync(0xffffffffu, pp1, 1);
    pp1 += __shfl_xor_sync(0xffffffffu, pp1, 2);
    float inv0 = rsqrtf(fmaxf(fabsf(pp0), 1e-8f));
    float inv1 = rsqrtf(fmaxf(fabsf(pp1), 1e-8f));
    float* c0p = ctx + ((size_t)((b*Sz + gq0)*Hz + h)) * DPH + colq;
    float* c1p = ctx + ((size_t)((b*Sz + gq1)*Hz + h)) * DPH + colq;
#pragma unroll
    for (int t = 0; t < 8; t++) {
        *(float2*)(c0p + t*8) = make_float2(cc[t][0]*inv0, cc[t][1]*inv0);
        *(float2*)(c1p + t*8) = make_float2(cc[t][2]*inv1, cc[t][3]*inv1);
    }
}

// ---------------------------------------------------------------------------
// Attention pass 2: recompute S, write normalized attn (incl. zero upper tri).
// ---------------------------------------------------------------------------
__global__ __launch_bounds__(256, 1) void pass2_kernel(
    float* __restrict__ attn, const float* __restrict__ scale_ptr)
{
    extern __shared__ char smraw[];
    const unsigned sb = (smem_u32(smraw) + 1023u) & ~1023u;

    const int blk = blockIdx.x;
    const int bh = blk & 15;
    const int qt = (NQT - 1) - (blk >> 4);
    const int q0 = qt * QT;

    const int tid = threadIdx.x;
    const int w = tid >> 5, l = tid & 31;

    const float inv_as = 1.f / scale_ptr[0];
    const __nv_bfloat16* Qhi = gPhi[0] + (size_t)bh * Sz * DPH;
    const __nv_bfloat16* Qlo = gPlo[0] + (size_t)bh * Sz * DPH;
    const __nv_bfloat16* Khi = gPhi[1] + (size_t)bh * Sz * DPH;
    const __nv_bfloat16* Klo = gPlo[1] + (size_t)bh * Sz * DPH;
    float* arow = attn + (size_t)bh * Sz * Sz;

    const int rr = tid >> 3, chk = tid & 7;

    auto issue_k = [&](int s, int kt) {
        unsigned base = sb + 32768u + (unsigned)s * 32768u;
        const int k0 = kt * QT;
#pragma unroll
        for (int it = 0; it < 4; it++) {
            int r = rr + it * 32;
            unsigned sw = SWZ((unsigned)(r * 128 + chk * 16));
            const size_t go = (size_t)(k0 + r) * DPH + chk * 8;
            cpa(base + sw,          Khi + go);
            cpa(base + 16384u + sw, Klo + go);
        }
        CP_COMMIT();
    };

#pragma unroll
    for (int it = 0; it < 4; it++) {
        int r = rr + it * 32;
        unsigned sw = SWZ((unsigned)(r * 128 + chk * 16));
        cpa(sb + sw,          Qhi + (size_t)(q0 + r) * DPH + chk * 8);
        cpa(sb + 16384u + sw, Qlo + (size_t)(q0 + r) * DPH + chk * 8);
    }
    CP_COMMIT();
    issue_k(0, 0);
    CP_WAIT(0);
    __syncthreads();

    unsigned qh[4][4], ql[4][4];
    {
        unsigned qoff = (unsigned)(w * 16 + (l & 15)) * 128 + ((l >> 4) * 16);
#pragma unroll
        for (int c = 0; c < 4; c++) {
            unsigned sw = SWZ(qoff + c * 32);
            ldsm4(sb + sw,          qh[c][0], qh[c][1], qh[c][2], qh[c][3]);
            ldsm4(sb + 16384u + sw, ql[c][0], ql[c][1], ql[c][2], ql[c][3]);
        }
    }

    const unsigned krow = (l & 7) + ((l & 16) >> 1);
    const unsigned kchalf = ((l >> 3) & 1) * 16;

    const int row0 = w * 16 + (l >> 2);
    const int gq0 = q0 + row0, gq1 = gq0 + 8;
    const int colq = (l & 3) * 2;
    const float il0 = 1.f / g_l[bh*Sz + gq0];
    const float il1 = 1.f / g_l[bh*Sz + gq1];

    for (int kt = 0; kt <= qt; ++kt) {
        const int k0 = kt * QT;
        if (kt < qt) { issue_k((kt + 1) & 1, kt + 1); CP_WAIT(1); }
        __syncthreads();
        const unsigned kb = sb + 32768u + (unsigned)(kt & 1) * 32768u;

        float sc[16][4];
#pragma unroll
        for (int i = 0; i < 16; i++)
#pragma unroll
            for (int j = 0; j < 4; j++) sc[i][j] = 0.f;
#pragma unroll
        for (int g = 0; g < 8; g++) {
            unsigned goff = (unsigned)(g * 16 + krow) * 128 + kchalf;
#pragma unroll
            for (int c = 0; c < 4; c++) {
                unsigned b0, b1, b2, b3, e0, e1, e2, e3;
                unsigned sw = SWZ(goff + c * 32);
                ldsm4(kb + sw,          b0, b1, b2, b3);
                ldsm4(kb + 16384u + sw, e0, e1, e2, e3);
                mma16816(sc[2*g],   qh[c], b0, b1);
                mma16816(sc[2*g+1], qh[c], b2, b3);
                mma16816(sc[2*g],   ql[c], b0, b1);
                mma16816(sc[2*g+1], ql[c], b2, b3);
                mma16816(sc[2*g],   qh[c], e0, e1);
                mma16816(sc[2*g+1], qh[c], e2, e3);
            }
        }

        const bool diag = (kt == qt);
        float* p0 = arow + (size_t)gq0 * Sz + k0 + colq;
        float* p1 = arow + (size_t)gq1 * Sz + k0 + colq;
#pragma unroll
        for (int t = 0; t < 16; t++) {
            int gk = k0 + t * 8 + colq;
            float v0 = __expf((2.f * sc[t][0] + 2.f) * inv_as) * il0;
            float v1 = __expf((2.f * sc[t][1] + 2.f) * inv_as) * il0;
            float v2 = __expf((2.f * sc[t][2] + 2.f) * inv_as) * il1;
            float v3 = __expf((2.f * sc[t][3] + 2.f) * inv_as) * il1;
            if (diag) {
                if (gk > gq0)     v0 = 0.f;
                if (gk + 1 > gq0) v1 = 0.f;
                if (gk > gq1)     v2 = 0.f;
                if (gk + 1 > gq1) v3 = 0.f;
            }
            *(float2*)(p0 + t*8) = make_float2(v0, v1);
            *(float2*)(p1 + t*8) = make_float2(v2, v3);
        }
        __syncthreads();
    }

    // zero the strict upper region (whole tiles right of the diagonal tile)
    const int z0 = (qt + 1) * QT;
    const int nz4 = (Sz - z0) >> 2;
    if (nz4 > 0) {
        const float4 zero = make_float4(0.f, 0.f, 0.f, 0.f);
        for (int idx = tid; idx < 128 * nz4; idx += 256) {
            int r = idx / nz4, c = idx % nz4;
            *(float4*)(arow + (size_t)(q0 + r) * Sz + z0 + c * 4) = zero;
        }
    }
}

extern "C" void kernel_launch(void* const* d_in, const int* in_sizes, int n_in,
                              void* d_out, int out_size)
{
    const float* key   = (const float*)d_in[0];
    const float* value = (const float*)d_in[1];
    const float* query = (const float*)d_in[2];
    const float* Wq = (const float*)d_in[4];
    const float* bq = (const float*)d_in[5];
    const float* sq = (const float*)d_in[6];
    const float* Wk = (const float*)d_in[7];
    const float* bk = (const float*)d_in[8];
    const float* sk = (const float*)d_in[9];
    const float* Wv = (const float*)d_in[10];
    const float* bv = (const float*)d_in[11];
    const float* sv = (const float*)d_in[12];
    const float* att_scale = (const float*)d_in[13];

    float* ctx  = (float*)d_out;
    float* attn = ctx + (size_t)Bz * Sz * Dz;

    dim3 gs(512, 6);
    split_kernel<<<gs, 256>>>(query, key, value, Wq, Wk, Wv);

    cudaFuncSetAttribute(proj_kernel, cudaFuncAttributeMaxDynamicSharedMemorySize, SMEM_PROJ);
    dim3 gp(Dz / 128, Mrows / 128, 3);
    proj_kernel<<<gp, 256, SMEM_PROJ>>>(bq, sq, bk, sk, bv, sv);

    cudaFuncSetAttribute(attn_kernel, cudaFuncAttributeMaxDynamicSharedMemorySize, SMEM_ATTN);
    attn_kernel<<<BHn * NQT, 256, SMEM_ATTN>>>(ctx, att_scale);

    cudaFuncSetAttribute(pass2_kernel, cudaFuncAttributeMaxDynamicSharedMemorySize, SMEM_P2);
    pass2_kernel<<<BHn * NQT, 256, SMEM_P2>>>(attn, att_scale);
}